// round 4
// baseline (speedup 1.0000x reference)
#include <cuda_runtime.h>
#include <cuda_bf16.h>
#include <mma.h>

using namespace nvcuda;

#define DMODEL 1024
#define NHEAD  16
#define DKH    64
#define DFF    4096
#define BATCH  4
#define SEQ    2048
#define MTOK   (BATCH * SEQ)

// ---------------- scratch (device globals; no allocation allowed) -------------
__device__ float g_q[MTOK * DMODEL];
__device__ float g_k[MTOK * DMODEL];
__device__ float g_v[MTOK * DMODEL];
__device__ float g_attn[MTOK * DMODEL];
__device__ float g_x1[MTOK * DMODEL];
__device__ float g_x2[MTOK * DMODEL];
__device__ float g_t[MTOK * DMODEL];
__device__ float g_h[MTOK * DFF];

// ---------------- tf32 WMMA GEMM: C = A(MxK) @ W(KxN) + bias, optional ReLU ---
template <int RELU>
__global__ __launch_bounds__(256) void tf32_gemm_bias(
    const float* __restrict__ A, const float* __restrict__ W,
    const float* __restrict__ bias, float* __restrict__ C,
    int M, int N, int K)
{
    constexpr int BM = 128, BN = 128, BK = 16;
    constexpr int LDA = BK + 8;   // 24 floats (96B, 16B-multiple)
    constexpr int LDB = BN + 8;   // 136 floats (544B, 16B-multiple)
    __shared__ float As[BM * LDA];
    __shared__ float Bs[BK * LDB];

    const int tid = threadIdx.x;
    const int wid = tid >> 5;
    const int wr  = wid >> 1;   // 0..3  (32-row stripe)
    const int wc  = wid & 1;    // 0..1  (64-col stripe)
    const int bm  = blockIdx.y * BM;
    const int bn  = blockIdx.x * BN;

    wmma::fragment<wmma::accumulator, 16, 16, 8, float> acc[2][4];

    // ---- init accumulators from bias (replicate bias across 16 smem rows) ----
    {
        int rr = tid >> 5;               // 0..7
        int n4 = (tid & 31) << 2;        // 0..124
        float4 bv = *reinterpret_cast<const float4*>(bias + bn + n4);
        *reinterpret_cast<float4*>(&Bs[rr * LDB + n4])       = bv;
        *reinterpret_cast<float4*>(&Bs[(rr + 8) * LDB + n4]) = bv;
        __syncthreads();
        #pragma unroll
        for (int fr = 0; fr < 2; fr++)
            #pragma unroll
            for (int fc = 0; fc < 4; fc++)
                wmma::load_matrix_sync(acc[fr][fc], &Bs[wc * 64 + fc * 16], LDB,
                                       wmma::mem_row_major);
        __syncthreads();
    }

    // ---- loaders: each thread moves 8 consecutive floats of A and of W ------
    const int ar  = tid >> 1;            // 0..127
    const int ak  = (tid & 1) << 3;      // 0 or 8
    const int brw = tid >> 4;            // 0..15
    const int bn4 = (tid & 15) << 3;     // 0..120
    const float* Ap = A + (size_t)(bm + ar) * K + ak;
    const float* Wp = W + (size_t)brw * N + bn + bn4;

    float4 pa0 = *reinterpret_cast<const float4*>(Ap);
    float4 pa1 = *reinterpret_cast<const float4*>(Ap + 4);
    float4 pb0 = *reinterpret_cast<const float4*>(Wp);
    float4 pb1 = *reinterpret_cast<const float4*>(Wp + 4);

    for (int k0 = 0; k0 < K; k0 += BK) {
        *reinterpret_cast<float4*>(&As[ar * LDA + ak])       = pa0;
        *reinterpret_cast<float4*>(&As[ar * LDA + ak + 4])   = pa1;
        *reinterpret_cast<float4*>(&Bs[brw * LDB + bn4])     = pb0;
        *reinterpret_cast<float4*>(&Bs[brw * LDB + bn4 + 4]) = pb1;
        __syncthreads();

        if (k0 + BK < K) {   // prefetch next K-panel into registers
            const float* Ap2 = Ap + k0 + BK;
            const float* Wp2 = Wp + (size_t)(k0 + BK) * N;
            pa0 = *reinterpret_cast<const float4*>(Ap2);
            pa1 = *reinterpret_cast<const float4*>(Ap2 + 4);
            pb0 = *reinterpret_cast<const float4*>(Wp2);
            pb1 = *reinterpret_cast<const float4*>(Wp2 + 4);
        }

        #pragma unroll
        for (int kk = 0; kk < BK; kk += 8) {
            wmma::fragment<wmma::matrix_a, 16, 16, 8, wmma::precision::tf32,
                           wmma::row_major> af[2];
            wmma::fragment<wmma::matrix_b, 16, 16, 8, wmma::precision::tf32,
                           wmma::row_major> bf[4];
            #pragma unroll
            for (int fr = 0; fr < 2; fr++) {
                wmma::load_matrix_sync(af[fr], &As[(wr * 32 + fr * 16) * LDA + kk], LDA);
                #pragma unroll
                for (int e = 0; e < af[fr].num_elements; e++)
                    af[fr].x[e] = wmma::__float_to_tf32(af[fr].x[e]);
            }
            #pragma unroll
            for (int fc = 0; fc < 4; fc++) {
                wmma::load_matrix_sync(bf[fc], &Bs[kk * LDB + wc * 64 + fc * 16], LDB);
                #pragma unroll
                for (int e = 0; e < bf[fc].num_elements; e++)
                    bf[fc].x[e] = wmma::__float_to_tf32(bf[fc].x[e]);
            }
            #pragma unroll
            for (int fr = 0; fr < 2; fr++)
                #pragma unroll
                for (int fc = 0; fc < 4; fc++)
                    wmma::mma_sync(acc[fr][fc], af[fr], bf[fc], acc[fr][fc]);
        }
        __syncthreads();
    }

    #pragma unroll
    for (int fr = 0; fr < 2; fr++)
        #pragma unroll
        for (int fc = 0; fc < 4; fc++) {
            if (RELU) {
                #pragma unroll
                for (int e = 0; e < acc[fr][fc].num_elements; e++)
                    acc[fr][fc].x[e] = fmaxf(acc[fr][fc].x[e], 0.0f);
            }
            float* cp = C + (size_t)(bm + wr * 32 + fr * 16) * N + bn + wc * 64 + fc * 16;
            wmma::store_matrix_sync(cp, acc[fr][fc], N, wmma::mem_row_major);
        }
}

// ---------------- flash attention (fp32, dk=64, 64x64 tiles) ------------------
// Q/K/V/O are [B*S, 1024]; head h occupies cols [h*64, h*64+64).
// tx = tid&15 owns score cols {tx+16i}; ty = tid>>4 owns rows {4*ty+j}.
// Smem rows are 64 floats with XOR swizzle: slot = d ^ ((row&15)<<2).
// K tile smem is reused to hold P after scores are consumed (48KB total).
__global__ __launch_bounds__(256) void flash_attn_kernel(
    const float* __restrict__ Qg, const float* __restrict__ Kg,
    const float* __restrict__ Vg, float* __restrict__ Og,
    int Sq, int Skv)
{
    __shared__ float Qs[64 * 64];
    __shared__ float Ks[64 * 64];   // scores consumed -> reused for P
    __shared__ float Vs[64 * 64];

    const int tid = threadIdx.x;
    const int tx  = tid & 15;
    const int ty  = tid >> 4;
    const int q0  = blockIdx.x * 64;
    const int h   = blockIdx.y;
    const int b   = blockIdx.z;
    const float scale = 0.125f;     // 1/sqrt(64)

    // load Q tile (pre-scaled, swizzled)
    #pragma unroll
    for (int i = 0; i < 4; i++) {
        int idx = tid + 256 * i;
        int r   = idx >> 4;
        int d4  = (idx & 15) << 2;
        float4 qv = *reinterpret_cast<const float4*>(
            Qg + (size_t)(b * Sq + q0 + r) * DMODEL + h * DKH + d4);
        qv.x *= scale; qv.y *= scale; qv.z *= scale; qv.w *= scale;
        *reinterpret_cast<float4*>(&Qs[r * 64 + (d4 ^ ((r & 15) << 2))]) = qv;
    }

    float m[4], l[4], o[4][4];
    #pragma unroll
    for (int j = 0; j < 4; j++) {
        m[j] = -1e30f; l[j] = 0.0f;
        o[j][0] = o[j][1] = o[j][2] = o[j][3] = 0.0f;
    }

    for (int kv0 = 0; kv0 < Skv; kv0 += 64) {
        __syncthreads();   // previous tile's P/V reads complete (also fences Qs on entry)
        #pragma unroll
        for (int i = 0; i < 4; i++) {
            int idx = tid + 256 * i;
            int c   = idx >> 4;
            int d4  = (idx & 15) << 2;
            int slot = c * 64 + (d4 ^ ((c & 15) << 2));
            size_t gbase = (size_t)(b * Skv + kv0 + c) * DMODEL + h * DKH + d4;
            *reinterpret_cast<float4*>(&Ks[slot]) =
                *reinterpret_cast<const float4*>(Kg + gbase);
            *reinterpret_cast<float4*>(&Vs[slot]) =
                *reinterpret_cast<const float4*>(Vg + gbase);
        }
        __syncthreads();

        // S = Q K^T  (4x4 micro-tile per thread)
        float s[4][4];
        #pragma unroll
        for (int j = 0; j < 4; j++)
            #pragma unroll
            for (int i = 0; i < 4; i++) s[j][i] = 0.0f;

        #pragma unroll
        for (int d0 = 0; d0 < 64; d0 += 4) {
            float4 qv[4], kv[4];
            #pragma unroll
            for (int j = 0; j < 4; j++) {
                int r = 4 * ty + j;
                qv[j] = *reinterpret_cast<const float4*>(
                    &Qs[r * 64 + (d0 ^ ((r & 15) << 2))]);
            }
            #pragma unroll
            for (int i = 0; i < 4; i++) {
                int c = tx + 16 * i;
                kv[i] = *reinterpret_cast<const float4*>(
                    &Ks[c * 64 + (d0 ^ ((c & 15) << 2))]);
            }
            #pragma unroll
            for (int j = 0; j < 4; j++)
                #pragma unroll
                for (int i = 0; i < 4; i++) {
                    s[j][i] += qv[j].x * kv[i].x;
                    s[j][i] += qv[j].y * kv[i].y;
                    s[j][i] += qv[j].z * kv[i].z;
                    s[j][i] += qv[j].w * kv[i].w;
                }
        }

        // online softmax (row reductions across 16-lane tx groups)
        float p[4][4];
        #pragma unroll
        for (int j = 0; j < 4; j++) {
            float mx = fmaxf(fmaxf(s[j][0], s[j][1]), fmaxf(s[j][2], s[j][3]));
            mx = fmaxf(mx, __shfl_xor_sync(0xffffffffu, mx, 8));
            mx = fmaxf(mx, __shfl_xor_sync(0xffffffffu, mx, 4));
            mx = fmaxf(mx, __shfl_xor_sync(0xffffffffu, mx, 2));
            mx = fmaxf(mx, __shfl_xor_sync(0xffffffffu, mx, 1));
            float mn = fmaxf(m[j], mx);
            float al = __expf(m[j] - mn);
            m[j] = mn;
            float ls = 0.0f;
            #pragma unroll
            for (int i = 0; i < 4; i++) { p[j][i] = __expf(s[j][i] - mn); ls += p[j][i]; }
            ls += __shfl_xor_sync(0xffffffffu, ls, 8);
            ls += __shfl_xor_sync(0xffffffffu, ls, 4);
            ls += __shfl_xor_sync(0xffffffffu, ls, 2);
            ls += __shfl_xor_sync(0xffffffffu, ls, 1);
            l[j] = l[j] * al + ls;
            o[j][0] *= al; o[j][1] *= al; o[j][2] *= al; o[j][3] *= al;
        }

        __syncthreads();   // everyone done reading Ks as K
        #pragma unroll
        for (int j = 0; j < 4; j++)
            #pragma unroll
            for (int i = 0; i < 4; i++)
                Ks[(4 * ty + j) * 64 + tx + 16 * i] = p[j][i];
        __syncthreads();   // P visible

        // O += P @ V   (thread owns rows 4*ty+j, d-cols 4*tx..4*tx+3)
        #pragma unroll
        for (int c4 = 0; c4 < 64; c4 += 4) {
            float pj[4][4];
            #pragma unroll
            for (int j = 0; j < 4; j++) {
                float4 t = *reinterpret_cast<const float4*>(&Ks[(4 * ty + j) * 64 + c4]);
                pj[j][0] = t.x; pj[j][1] = t.y; pj[j][2] = t.z; pj[j][3] = t.w;
            }
            #pragma unroll
            for (int cc = 0; cc < 4; cc++) {
                int c = c4 + cc;
                float4 vv = *reinterpret_cast<const float4*>(
                    &Vs[c * 64 + ((4 * tx) ^ ((c & 15) << 2))]);
                #pragma unroll
                for (int j = 0; j < 4; j++) {
                    o[j][0] += pj[j][cc] * vv.x;
                    o[j][1] += pj[j][cc] * vv.y;
                    o[j][2] += pj[j][cc] * vv.z;
                    o[j][3] += pj[j][cc] * vv.w;
                }
            }
        }
    }

    #pragma unroll
    for (int j = 0; j < 4; j++) {
        float inv = 1.0f / l[j];
        float4 ov = make_float4(o[j][0] * inv, o[j][1] * inv,
                                o[j][2] * inv, o[j][3] * inv);
        *reinterpret_cast<float4*>(
            Og + (size_t)(b * Sq + q0 + 4 * ty + j) * DMODEL + h * DKH + 4 * tx) = ov;
    }
}

// ---------------- out = LayerNorm(a + c) * g + b ------------------------------
__global__ __launch_bounds__(256) void add_ln_kernel(
    const float* __restrict__ a, const float* __restrict__ cadd,
    const float* __restrict__ g, const float* __restrict__ be,
    float* __restrict__ out)
{
    __shared__ float red[16];
    const int row = blockIdx.x;
    const int tid = threadIdx.x;
    const size_t base = (size_t)row * DMODEL + tid * 4;

    float4 av = *reinterpret_cast<const float4*>(a + base);
    float4 cv = *reinterpret_cast<const float4*>(cadd + base);
    float x0 = av.x + cv.x, x1 = av.y + cv.y;
    float x2 = av.z + cv.z, x3 = av.w + cv.w;

    float s  = x0 + x1 + x2 + x3;
    float ss = x0 * x0 + x1 * x1 + x2 * x2 + x3 * x3;
    #pragma unroll
    for (int off = 16; off; off >>= 1) {
        s  += __shfl_xor_sync(0xffffffffu, s,  off);
        ss += __shfl_xor_sync(0xffffffffu, ss, off);
    }
    if ((tid & 31) == 0) { red[tid >> 5] = s; red[8 + (tid >> 5)] = ss; }
    __syncthreads();
    float ts = 0.0f, tss = 0.0f;
    #pragma unroll
    for (int i = 0; i < 8; i++) { ts += red[i]; tss += red[8 + i]; }

    const float mu  = ts * (1.0f / DMODEL);
    const float var = tss * (1.0f / DMODEL) - mu * mu;
    const float inv = rsqrtf(var + 1e-5f);

    float4 gv = *reinterpret_cast<const float4*>(g  + tid * 4);
    float4 bv = *reinterpret_cast<const float4*>(be + tid * 4);
    float4 ov;
    ov.x = (x0 - mu) * inv * gv.x + bv.x;
    ov.y = (x1 - mu) * inv * gv.y + bv.y;
    ov.z = (x2 - mu) * inv * gv.z + bv.z;
    ov.w = (x3 - mu) * inv * gv.w + bv.w;
    *reinterpret_cast<float4*>(out + base) = ov;
}

// ------------------------------- host driver ----------------------------------
static inline void launch_gemm(const float* A, const float* W, const float* B,
                               float* C, int M, int N, int K, int relu)
{
    dim3 grid(N / 128, M / 128), blk(256);
    if (relu) tf32_gemm_bias<1><<<grid, blk>>>(A, W, B, C, M, N, K);
    else      tf32_gemm_bias<0><<<grid, blk>>>(A, W, B, C, M, N, K);
}

extern "C" void kernel_launch(void* const* d_in, const int* in_sizes, int n_in,
                              void* d_out, int out_size)
{
    const float* src   = (const float*)d_in[0];
    const float* tgt   = (const float*)d_in[1];
    const float* sa_wq = (const float*)d_in[2];
    const float* sa_bq = (const float*)d_in[3];
    const float* sa_wk = (const float*)d_in[4];
    const float* sa_bk = (const float*)d_in[5];
    const float* sa_wv = (const float*)d_in[6];
    const float* sa_bv = (const float*)d_in[7];
    const float* sa_wo = (const float*)d_in[8];
    const float* sa_bo = (const float*)d_in[9];
    const float* ca_wq = (const float*)d_in[10];
    const float* ca_bq = (const float*)d_in[11];
    const float* ca_wk = (const float*)d_in[12];
    const float* ca_bk = (const float*)d_in[13];
    const float* ca_wv = (const float*)d_in[14];
    const float* ca_bv = (const float*)d_in[15];
    const float* ca_wo = (const float*)d_in[16];
    const float* ca_bo = (const float*)d_in[17];
    const float* ff_w1 = (const float*)d_in[18];
    const float* ff_b1 = (const float*)d_in[19];
    const float* ff_w2 = (const float*)d_in[20];
    const float* ff_b2 = (const float*)d_in[21];
    const float* ln1_g = (const float*)d_in[22];
    const float* ln1_b = (const float*)d_in[23];
    const float* ln2_g = (const float*)d_in[24];
    const float* ln2_b = (const float*)d_in[25];
    const float* ln3_g = (const float*)d_in[26];
    const float* ln3_b = (const float*)d_in[27];
    float* out = (float*)d_out;

    float *q, *k, *v, *attn, *x1, *x2, *t, *h;
    cudaGetSymbolAddress((void**)&q,    g_q);
    cudaGetSymbolAddress((void**)&k,    g_k);
    cudaGetSymbolAddress((void**)&v,    g_v);
    cudaGetSymbolAddress((void**)&attn, g_attn);
    cudaGetSymbolAddress((void**)&x1,   g_x1);
    cudaGetSymbolAddress((void**)&x2,   g_x2);
    cudaGetSymbolAddress((void**)&t,    g_t);
    cudaGetSymbolAddress((void**)&h,    g_h);

    dim3 fgrid(SEQ / 64, NHEAD, BATCH), blk(256);

    // ---- self-attention block ----
    launch_gemm(tgt, sa_wq, sa_bq, q, MTOK, DMODEL, DMODEL, 0);
    launch_gemm(tgt, sa_wk, sa_bk, k, MTOK, DMODEL, DMODEL, 0);
    launch_gemm(tgt, sa_wv, sa_bv, v, MTOK, DMODEL, DMODEL, 0);
    flash_attn_kernel<<<fgrid, blk>>>(q, k, v, attn, SEQ, SEQ);
    launch_gemm(attn, sa_wo, sa_bo, t, MTOK, DMODEL, DMODEL, 0);
    add_ln_kernel<<<MTOK, blk>>>(tgt, t, ln1_g, ln1_b, x1);

    // ---- cross-attention block ----
    launch_gemm(x1,  ca_wq, ca_bq, q, MTOK, DMODEL, DMODEL, 0);
    launch_gemm(src, ca_wk, ca_bk, k, MTOK, DMODEL, DMODEL, 0);
    launch_gemm(src, ca_wv, ca_bv, v, MTOK, DMODEL, DMODEL, 0);
    flash_attn_kernel<<<fgrid, blk>>>(q, k, v, attn, SEQ, SEQ);
    launch_gemm(attn, ca_wo, ca_bo, t, MTOK, DMODEL, DMODEL, 0);
    add_ln_kernel<<<MTOK, blk>>>(x1, t, ln2_g, ln2_b, x2);

    // ---- feed-forward block ----
    launch_gemm(x2, ff_w1, ff_b1, h, MTOK, DFF, DMODEL, 1);
    launch_gemm(h,  ff_w2, ff_b2, t, MTOK, DMODEL, DFF, 0);
    add_ln_kernel<<<MTOK, blk>>>(x2, t, ln3_g, ln3_b, out);
}

// round 6
// speedup vs baseline: 1.4823x; 1.4823x over previous
#include <cuda_runtime.h>
#include <cuda_bf16.h>
#include <mma.h>

using namespace nvcuda;

#define DMODEL 1024
#define NHEAD  16
#define DKH    64
#define DFF    4096
#define BATCH  4
#define SEQ    2048
#define MTOK   (BATCH * SEQ)

// ---------------- scratch (device globals; no allocation allowed) -------------
__device__ float g_q[MTOK * DMODEL];
__device__ float g_k[MTOK * DMODEL];
__device__ float g_v[MTOK * DMODEL];
__device__ float g_attn[MTOK * DMODEL];
__device__ float g_x1[MTOK * DMODEL];
__device__ float g_x2[MTOK * DMODEL];
__device__ float g_t[MTOK * DMODEL];
__device__ float g_h[MTOK * DFF];

// ---------------- tf32 WMMA GEMM: C = A(MxK) @ W(KxN) + bias, optional ReLU ---
template <int RELU>
__global__ __launch_bounds__(256) void tf32_gemm_bias(
    const float* __restrict__ A, const float* __restrict__ W,
    const float* __restrict__ bias, float* __restrict__ C,
    int M, int N, int K)
{
    constexpr int BM = 128, BN = 128, BK = 16;
    constexpr int LDA = BK + 8;   // 24 floats
    constexpr int LDB = BN + 8;   // 136 floats
    __shared__ float As[BM * LDA];
    __shared__ float Bs[BK * LDB];

    const int tid = threadIdx.x;
    const int wid = tid >> 5;
    const int wr  = wid >> 1;
    const int wc  = wid & 1;
    const int bm  = blockIdx.y * BM;
    const int bn  = blockIdx.x * BN;

    wmma::fragment<wmma::accumulator, 16, 16, 8, float> acc[2][4];

    {
        int rr = tid >> 5;
        int n4 = (tid & 31) << 2;
        float4 bv = *reinterpret_cast<const float4*>(bias + bn + n4);
        *reinterpret_cast<float4*>(&Bs[rr * LDB + n4])       = bv;
        *reinterpret_cast<float4*>(&Bs[(rr + 8) * LDB + n4]) = bv;
        __syncthreads();
        #pragma unroll
        for (int fr = 0; fr < 2; fr++)
            #pragma unroll
            for (int fc = 0; fc < 4; fc++)
                wmma::load_matrix_sync(acc[fr][fc], &Bs[wc * 64 + fc * 16], LDB,
                                       wmma::mem_row_major);
        __syncthreads();
    }

    const int ar  = tid >> 1;
    const int ak  = (tid & 1) << 3;
    const int brw = tid >> 4;
    const int bn4 = (tid & 15) << 3;
    const float* Ap = A + (size_t)(bm + ar) * K + ak;
    const float* Wp = W + (size_t)brw * N + bn + bn4;

    float4 pa0 = *reinterpret_cast<const float4*>(Ap);
    float4 pa1 = *reinterpret_cast<const float4*>(Ap + 4);
    float4 pb0 = *reinterpret_cast<const float4*>(Wp);
    float4 pb1 = *reinterpret_cast<const float4*>(Wp + 4);

    for (int k0 = 0; k0 < K; k0 += BK) {
        *reinterpret_cast<float4*>(&As[ar * LDA + ak])       = pa0;
        *reinterpret_cast<float4*>(&As[ar * LDA + ak + 4])   = pa1;
        *reinterpret_cast<float4*>(&Bs[brw * LDB + bn4])     = pb0;
        *reinterpret_cast<float4*>(&Bs[brw * LDB + bn4 + 4]) = pb1;
        __syncthreads();

        if (k0 + BK < K) {
            const float* Ap2 = Ap + k0 + BK;
            const float* Wp2 = Wp + (size_t)(k0 + BK) * N;
            pa0 = *reinterpret_cast<const float4*>(Ap2);
            pa1 = *reinterpret_cast<const float4*>(Ap2 + 4);
            pb0 = *reinterpret_cast<const float4*>(Wp2);
            pb1 = *reinterpret_cast<const float4*>(Wp2 + 4);
        }

        #pragma unroll
        for (int kk = 0; kk < BK; kk += 8) {
            wmma::fragment<wmma::matrix_a, 16, 16, 8, wmma::precision::tf32,
                           wmma::row_major> af[2];
            wmma::fragment<wmma::matrix_b, 16, 16, 8, wmma::precision::tf32,
                           wmma::row_major> bf[4];
            #pragma unroll
            for (int fr = 0; fr < 2; fr++) {
                wmma::load_matrix_sync(af[fr], &As[(wr * 32 + fr * 16) * LDA + kk], LDA);
                #pragma unroll
                for (int e = 0; e < af[fr].num_elements; e++)
                    af[fr].x[e] = wmma::__float_to_tf32(af[fr].x[e]);
            }
            #pragma unroll
            for (int fc = 0; fc < 4; fc++) {
                wmma::load_matrix_sync(bf[fc], &Bs[kk * LDB + wc * 64 + fc * 16], LDB);
                #pragma unroll
                for (int e = 0; e < bf[fc].num_elements; e++)
                    bf[fc].x[e] = wmma::__float_to_tf32(bf[fc].x[e]);
            }
            #pragma unroll
            for (int fr = 0; fr < 2; fr++)
                #pragma unroll
                for (int fc = 0; fc < 4; fc++)
                    wmma::mma_sync(acc[fr][fc], af[fr], bf[fc], acc[fr][fc]);
        }
        __syncthreads();
    }

    #pragma unroll
    for (int fr = 0; fr < 2; fr++)
        #pragma unroll
        for (int fc = 0; fc < 4; fc++) {
            if (RELU) {
                #pragma unroll
                for (int e = 0; e < acc[fr][fc].num_elements; e++)
                    acc[fr][fc].x[e] = fmaxf(acc[fr][fc].x[e], 0.0f);
            }
            float* cp = C + (size_t)(bm + wr * 32 + fr * 16) * N + bn + wc * 64 + fc * 16;
            wmma::store_matrix_sync(cp, acc[fr][fc], N, wmma::mem_row_major);
        }
}

// ============== tensor-core flash attention (tf32 mma.sync, dk=64) ============
// CTA: 256 threads = 8 warps, 128 Q rows (16 per warp). KV tiled by 64.
// Q fragments live in registers for the whole KV loop. K/V/P staged in smem
// pre-converted to tf32. mma.m16n8k8 documented layouts:
//   A: a0(r0,c), a1(r0+8,c), a2(r0,c+4), a3(r0+8,c+4)   r0=lane>>2, c=lane&3
//   B: b0(k=lane&3, n=lane>>2), b1(k+4, n)
//   C: c0(r0,2j), c1(r0,2j+1), c2(r0+8,2j), c3(r0+8,2j+1)  j=lane&3
// Pads: LDK=LDP=68 (banks 4r+c conflict-free), LDV=72 (banks 8r+c conflict-free).
#define FLDK 68
#define FLDV 72
#define FLDP 68
#define FKS_OFF 0
#define FVS_OFF (64 * FLDK)                 // 4352
#define FPS_OFF (FVS_OFF + 64 * FLDV)       // 8960
#define FSMEM_FLOATS (FPS_OFF + 128 * FLDP) // 17664
#define FSMEM_BYTES  (FSMEM_FLOATS * 4)     // 70656

__device__ __forceinline__ unsigned f2tf(float x) {
    unsigned u;
    asm("cvt.rna.tf32.f32 %0, %1;" : "=r"(u) : "f"(x));
    return u;
}

__device__ __forceinline__ void mma_tf32(float* d, const unsigned* a,
                                         const unsigned* b) {
    asm volatile(
        "mma.sync.aligned.m16n8k8.row.col.f32.tf32.tf32.f32 "
        "{%0,%1,%2,%3}, {%4,%5,%6,%7}, {%8,%9}, {%0,%1,%2,%3};\n"
        : "+f"(d[0]), "+f"(d[1]), "+f"(d[2]), "+f"(d[3])
        : "r"(a[0]), "r"(a[1]), "r"(a[2]), "r"(a[3]), "r"(b[0]), "r"(b[1]));
}

__global__ __launch_bounds__(256) void flash_attn_tc(
    const float* __restrict__ Qg, const float* __restrict__ Kg,
    const float* __restrict__ Vg, float* __restrict__ Og,
    int Sq, int Skv)
{
    extern __shared__ float fsm[];
    unsigned* smu = reinterpret_cast<unsigned*>(fsm);

    const int tid  = threadIdx.x;
    const int lane = tid & 31;
    const int w    = tid >> 5;
    const int q0   = blockIdx.x * 128;
    const int h    = blockIdx.y;
    const int b    = blockIdx.z;
    const int r0   = lane >> 2;
    const int cq   = lane & 3;
    const float scale = 0.125f;   // 1/sqrt(64)

    // ---- Q fragments in registers (scaled + tf32) ----
    unsigned qa[8][4];
    {
        const float* Qb = Qg + (size_t)(b * Sq + q0 + w * 16) * DMODEL + h * DKH;
        #pragma unroll
        for (int ds = 0; ds < 8; ds++) {
            int c = ds * 8 + cq;
            qa[ds][0] = f2tf(scale * Qb[(size_t)r0       * DMODEL + c]);
            qa[ds][1] = f2tf(scale * Qb[(size_t)(r0 + 8) * DMODEL + c]);
            qa[ds][2] = f2tf(scale * Qb[(size_t)r0       * DMODEL + c + 4]);
            qa[ds][3] = f2tf(scale * Qb[(size_t)(r0 + 8) * DMODEL + c + 4]);
        }
    }

    float m0 = -1e30f, m1 = -1e30f, l0 = 0.0f, l1 = 0.0f;
    float o[8][4];
    #pragma unroll
    for (int nt = 0; nt < 8; nt++)
        o[nt][0] = o[nt][1] = o[nt][2] = o[nt][3] = 0.0f;

    unsigned* const pbase = smu + FPS_OFF + (w * 16) * FLDP;

    for (int kv0 = 0; kv0 < Skv; kv0 += 64) {
        __syncthreads();   // previous step's K/V reads complete
        // ---- stage K,V tiles as tf32 ----
        #pragma unroll
        for (int i = 0; i < 4; i++) {
            int idx = tid + 256 * i;
            int r   = idx >> 4;
            int c4  = (idx & 15) << 2;
            size_t gb = (size_t)(b * Skv + kv0 + r) * DMODEL + h * DKH + c4;
            float4 k4 = *reinterpret_cast<const float4*>(Kg + gb);
            float4 v4 = *reinterpret_cast<const float4*>(Vg + gb);
            unsigned* kd = smu + FKS_OFF + r * FLDK + c4;
            kd[0] = f2tf(k4.x); kd[1] = f2tf(k4.y);
            kd[2] = f2tf(k4.z); kd[3] = f2tf(k4.w);
            unsigned* vd = smu + FVS_OFF + r * FLDV + c4;
            vd[0] = f2tf(v4.x); vd[1] = f2tf(v4.y);
            vd[2] = f2tf(v4.z); vd[3] = f2tf(v4.w);
        }
        __syncthreads();

        // ---- S = (Q*scale) K^T : 8 n-tiles of m16n8, k-loop over d ----
        float s[8][4];
        #pragma unroll
        for (int nt = 0; nt < 8; nt++)
            s[nt][0] = s[nt][1] = s[nt][2] = s[nt][3] = 0.0f;

        #pragma unroll
        for (int ds = 0; ds < 8; ds++) {
            #pragma unroll
            for (int nt = 0; nt < 8; nt++) {
                const unsigned* kp = smu + FKS_OFF + (nt * 8 + r0) * FLDK + ds * 8 + cq;
                unsigned bb[2] = { kp[0], kp[4] };
                mma_tf32(s[nt], qa[ds], bb);
            }
        }

        // ---- online softmax (rows r0 and r0+8, reduced within quad) ----
        float mx0 = s[0][0], mx1 = s[0][2];
        #pragma unroll
        for (int nt = 0; nt < 8; nt++) {
            mx0 = fmaxf(mx0, fmaxf(s[nt][0], s[nt][1]));
            mx1 = fmaxf(mx1, fmaxf(s[nt][2], s[nt][3]));
        }
        mx0 = fmaxf(mx0, __shfl_xor_sync(0xffffffffu, mx0, 1));
        mx0 = fmaxf(mx0, __shfl_xor_sync(0xffffffffu, mx0, 2));
        mx1 = fmaxf(mx1, __shfl_xor_sync(0xffffffffu, mx1, 1));
        mx1 = fmaxf(mx1, __shfl_xor_sync(0xffffffffu, mx1, 2));

        float mn0 = fmaxf(m0, mx0), mn1 = fmaxf(m1, mx1);
        float al0 = __expf(m0 - mn0), al1 = __expf(m1 - mn1);
        m0 = mn0; m1 = mn1;

        float sum0 = 0.0f, sum1 = 0.0f;
        #pragma unroll
        for (int nt = 0; nt < 8; nt++) {
            s[nt][0] = __expf(s[nt][0] - mn0);
            s[nt][1] = __expf(s[nt][1] - mn0);
            s[nt][2] = __expf(s[nt][2] - mn1);
            s[nt][3] = __expf(s[nt][3] - mn1);
            sum0 += s[nt][0] + s[nt][1];
            sum1 += s[nt][2] + s[nt][3];
        }
        sum0 += __shfl_xor_sync(0xffffffffu, sum0, 1);
        sum0 += __shfl_xor_sync(0xffffffffu, sum0, 2);
        sum1 += __shfl_xor_sync(0xffffffffu, sum1, 1);
        sum1 += __shfl_xor_sync(0xffffffffu, sum1, 2);
        l0 = l0 * al0 + sum0;
        l1 = l1 * al1 + sum1;

        // ---- rescale O, write P (tf32) to the warp-private smem strip ----
        #pragma unroll
        for (int nt = 0; nt < 8; nt++) {
            o[nt][0] *= al0; o[nt][1] *= al0;
            o[nt][2] *= al1; o[nt][3] *= al1;
            uint2 p01 = make_uint2(f2tf(s[nt][0]), f2tf(s[nt][1]));
            uint2 p23 = make_uint2(f2tf(s[nt][2]), f2tf(s[nt][3]));
            *reinterpret_cast<uint2*>(pbase + r0 * FLDP + nt * 8 + 2 * cq)       = p01;
            *reinterpret_cast<uint2*>(pbase + (r0 + 8) * FLDP + nt * 8 + 2 * cq) = p23;
        }
        __syncwarp();   // P strip is warp-private: warp-level ordering suffices

        // ---- O += P @ V ----
        #pragma unroll
        for (int kk = 0; kk < 8; kk++) {
            const unsigned* pp = pbase + r0 * FLDP + kk * 8 + cq;
            unsigned pa[4];
            pa[0] = pp[0];
            pa[1] = pp[8 * FLDP];
            pa[2] = pp[4];
            pa[3] = pp[8 * FLDP + 4];
            #pragma unroll
            for (int nt = 0; nt < 8; nt++) {
                const unsigned* vp = smu + FVS_OFF + (kk * 8 + cq) * FLDV + nt * 8 + r0;
                unsigned bb[2] = { vp[0], vp[4 * FLDV] };
                mma_tf32(o[nt], pa, bb);
            }
        }
    }

    // ---- epilogue: O / l ----
    const float i0 = 1.0f / l0, i1 = 1.0f / l1;
    float* Ob = Og + (size_t)(b * Sq + q0 + w * 16) * DMODEL + h * DKH;
    #pragma unroll
    for (int nt = 0; nt < 8; nt++) {
        float2 v0 = make_float2(o[nt][0] * i0, o[nt][1] * i0);
        float2 v1 = make_float2(o[nt][2] * i1, o[nt][3] * i1);
        *reinterpret_cast<float2*>(Ob + (size_t)r0 * DMODEL + nt * 8 + 2 * cq)       = v0;
        *reinterpret_cast<float2*>(Ob + (size_t)(r0 + 8) * DMODEL + nt * 8 + 2 * cq) = v1;
    }
}

// ---------------- out = LayerNorm(a + c) * g + b ------------------------------
__global__ __launch_bounds__(256) void add_ln_kernel(
    const float* __restrict__ a, const float* __restrict__ cadd,
    const float* __restrict__ g, const float* __restrict__ be,
    float* __restrict__ out)
{
    __shared__ float red[16];
    const int row = blockIdx.x;
    const int tid = threadIdx.x;
    const size_t base = (size_t)row * DMODEL + tid * 4;

    float4 av = *reinterpret_cast<const float4*>(a + base);
    float4 cv = *reinterpret_cast<const float4*>(cadd + base);
    float x0 = av.x + cv.x, x1 = av.y + cv.y;
    float x2 = av.z + cv.z, x3 = av.w + cv.w;

    float s  = x0 + x1 + x2 + x3;
    float ss = x0 * x0 + x1 * x1 + x2 * x2 + x3 * x3;
    #pragma unroll
    for (int off = 16; off; off >>= 1) {
        s  += __shfl_xor_sync(0xffffffffu, s,  off);
        ss += __shfl_xor_sync(0xffffffffu, ss, off);
    }
    if ((tid & 31) == 0) { red[tid >> 5] = s; red[8 + (tid >> 5)] = ss; }
    __syncthreads();
    float ts = 0.0f, tss = 0.0f;
    #pragma unroll
    for (int i = 0; i < 8; i++) { ts += red[i]; tss += red[8 + i]; }

    const float mu  = ts * (1.0f / DMODEL);
    const float var = tss * (1.0f / DMODEL) - mu * mu;
    const float inv = rsqrtf(var + 1e-5f);

    float4 gv = *reinterpret_cast<const float4*>(g  + tid * 4);
    float4 bv = *reinterpret_cast<const float4*>(be + tid * 4);
    float4 ov;
    ov.x = (x0 - mu) * inv * gv.x + bv.x;
    ov.y = (x1 - mu) * inv * gv.y + bv.y;
    ov.z = (x2 - mu) * inv * gv.z + bv.z;
    ov.w = (x3 - mu) * inv * gv.w + bv.w;
    *reinterpret_cast<float4*>(out + base) = ov;
}

// ------------------------------- host driver ----------------------------------
static inline void launch_gemm(const float* A, const float* W, const float* B,
                               float* C, int M, int N, int K, int relu)
{
    dim3 grid(N / 128, M / 128), blk(256);
    if (relu) tf32_gemm_bias<1><<<grid, blk>>>(A, W, B, C, M, N, K);
    else      tf32_gemm_bias<0><<<grid, blk>>>(A, W, B, C, M, N, K);
}

extern "C" void kernel_launch(void* const* d_in, const int* in_sizes, int n_in,
                              void* d_out, int out_size)
{
    const float* src   = (const float*)d_in[0];
    const float* tgt   = (const float*)d_in[1];
    const float* sa_wq = (const float*)d_in[2];
    const float* sa_bq = (const float*)d_in[3];
    const float* sa_wk = (const float*)d_in[4];
    const float* sa_bk = (const float*)d_in[5];
    const float* sa_wv = (const float*)d_in[6];
    const float* sa_bv = (const float*)d_in[7];
    const float* sa_wo = (const float*)d_in[8];
    const float* sa_bo = (const float*)d_in[9];
    const float* ca_wq = (const float*)d_in[10];
    const float* ca_bq = (const float*)d_in[11];
    const float* ca_wk = (const float*)d_in[12];
    const float* ca_bk = (const float*)d_in[13];
    const float* ca_wv = (const float*)d_in[14];
    const float* ca_bv = (const float*)d_in[15];
    const float* ca_wo = (const float*)d_in[16];
    const float* ca_bo = (const float*)d_in[17];
    const float* ff_w1 = (const float*)d_in[18];
    const float* ff_b1 = (const float*)d_in[19];
    const float* ff_w2 = (const float*)d_in[20];
    const float* ff_b2 = (const float*)d_in[21];
    const float* ln1_g = (const float*)d_in[22];
    const float* ln1_b = (const float*)d_in[23];
    const float* ln2_g = (const float*)d_in[24];
    const float* ln2_b = (const float*)d_in[25];
    const float* ln3_g = (const float*)d_in[26];
    const float* ln3_b = (const float*)d_in[27];
    float* out = (float*)d_out;

    float *q, *k, *v, *attn, *x1, *x2, *t, *h;
    cudaGetSymbolAddress((void**)&q,    g_q);
    cudaGetSymbolAddress((void**)&k,    g_k);
    cudaGetSymbolAddress((void**)&v,    g_v);
    cudaGetSymbolAddress((void**)&attn, g_attn);
    cudaGetSymbolAddress((void**)&x1,   g_x1);
    cudaGetSymbolAddress((void**)&x2,   g_x2);
    cudaGetSymbolAddress((void**)&t,    g_t);
    cudaGetSymbolAddress((void**)&h,    g_h);

    cudaFuncSetAttribute(flash_attn_tc,
                         cudaFuncAttributeMaxDynamicSharedMemorySize, FSMEM_BYTES);

    dim3 fgrid(SEQ / 128, NHEAD, BATCH), blk(256);

    // ---- self-attention block ----
    launch_gemm(tgt, sa_wq, sa_bq, q, MTOK, DMODEL, DMODEL, 0);
    launch_gemm(tgt, sa_wk, sa_bk, k, MTOK, DMODEL, DMODEL, 0);
    launch_gemm(tgt, sa_wv, sa_bv, v, MTOK, DMODEL, DMODEL, 0);
    flash_attn_tc<<<fgrid, blk, FSMEM_BYTES>>>(q, k, v, attn, SEQ, SEQ);
    launch_gemm(attn, sa_wo, sa_bo, t, MTOK, DMODEL, DMODEL, 0);
    add_ln_kernel<<<MTOK, blk>>>(tgt, t, ln1_g, ln1_b, x1);

    // ---- cross-attention block ----
    launch_gemm(x1,  ca_wq, ca_bq, q, MTOK, DMODEL, DMODEL, 0);
    launch_gemm(src, ca_wk, ca_bk, k, MTOK, DMODEL, DMODEL, 0);
    launch_gemm(src, ca_wv, ca_bv, v, MTOK, DMODEL, DMODEL, 0);
    flash_attn_tc<<<fgrid, blk, FSMEM_BYTES>>>(q, k, v, attn, SEQ, SEQ);
    launch_gemm(attn, ca_wo, ca_bo, t, MTOK, DMODEL, DMODEL, 0);
    add_ln_kernel<<<MTOK, blk>>>(x1, t, ln2_g, ln2_b, x2);

    // ---- feed-forward block ----
    launch_gemm(x2, ff_w1, ff_b1, h, MTOK, DFF, DMODEL, 1);
    launch_gemm(h,  ff_w2, ff_b2, t, MTOK, DMODEL, DFF, 0);
    add_ln_kernel<<<MTOK, blk>>>(x2, t, ln3_g, ln3_b, out);
}

// round 8
// speedup vs baseline: 2.0419x; 1.3775x over previous
#include <cuda_runtime.h>
#include <cuda_bf16.h>
#include <mma.h>

using namespace nvcuda;

#define DMODEL 1024
#define NHEAD  16
#define DKH    64
#define DFF    4096
#define BATCH  4
#define SEQ    2048
#define MTOK   (BATCH * SEQ)

// ---------------- scratch (device globals; no allocation allowed) -------------
__device__ float g_q[MTOK * DMODEL];
__device__ float g_k[MTOK * DMODEL];
__device__ float g_v[MTOK * DMODEL];
__device__ float g_attn[MTOK * DMODEL];
__device__ float g_x1[MTOK * DMODEL];
__device__ float g_x2[MTOK * DMODEL];
__device__ float g_t[MTOK * DMODEL];
__device__ float g_h[MTOK * DFF];
__device__ __nv_bfloat16 g_a16[MTOK * DFF];     // bf16 A-operand scratch (64MB)
__device__ __nv_bfloat16 g_w16[DMODEL * DFF];   // bf16 W-operand scratch (8MB)

// ---------------- fp32 -> bf16 conversion (vectorized) ------------------------
__global__ __launch_bounds__(256) void f2bf_kernel(
    const float* __restrict__ in, __nv_bfloat16* __restrict__ out, int n4)
{
    int i = blockIdx.x * blockDim.x + threadIdx.x;
    if (i < n4) {
        float4 v = reinterpret_cast<const float4*>(in)[i];
        __nv_bfloat162 a = __floats2bfloat162_rn(v.x, v.y);
        __nv_bfloat162 b = __floats2bfloat162_rn(v.z, v.w);
        uint2 u;
        u.x = *reinterpret_cast<unsigned*>(&a);
        u.y = *reinterpret_cast<unsigned*>(&b);
        reinterpret_cast<uint2*>(out)[i] = u;
    }
}

// ---------------- cp.async helpers --------------------------------------------
__device__ __forceinline__ void cp16(void* dst, const void* src) {
    unsigned d = (unsigned)__cvta_generic_to_shared(dst);
    asm volatile("cp.async.cg.shared.global [%0], [%1], 16;\n" :: "r"(d), "l"(src));
}

// ---------------- bf16 WMMA GEMM: C = A(MxK) @ W(KxN) + bias, optional ReLU ---
// A, W are bf16 row-major; bias/output fp32. BM=BN=128, BK=32, double-buffered
// cp.async smem, 8 warps (warp tile 32x64, m16n16k16 fragments).
template <int RELU>
__global__ __launch_bounds__(256, 2) void bf16_gemm_bias(
    const __nv_bfloat16* __restrict__ A, const __nv_bfloat16* __restrict__ W,
    const float* __restrict__ bias, float* __restrict__ C,
    int M, int N, int K)
{
    constexpr int BM = 128, BN = 128, BK = 32;
    constexpr int LDA = 40;    // elements; row stride 80B (16B multiple)
    constexpr int LDB = 136;   // elements; row stride 272B (16B multiple)
    __shared__ __nv_bfloat16 As[2][BM * LDA];
    __shared__ __nv_bfloat16 Bs[2][BK * LDB];

    const int tid = threadIdx.x;
    const int wid = tid >> 5;
    const int wr  = wid >> 1;    // 0..3
    const int wc  = wid & 1;     // 0..1
    const int bm  = blockIdx.y * BM;
    const int bn  = blockIdx.x * BN;

    wmma::fragment<wmma::accumulator, 16, 16, 16, float> acc[2][4];

    // ---- init accumulators from bias (stage replicated rows as fp32 in As) ---
    {
        float* fs = reinterpret_cast<float*>(As);
        int rr = tid >> 5;
        int n4 = (tid & 31) << 2;
        float4 bv = *reinterpret_cast<const float4*>(bias + bn + n4);
        *reinterpret_cast<float4*>(&fs[rr * 136 + n4])       = bv;
        *reinterpret_cast<float4*>(&fs[(rr + 8) * 136 + n4]) = bv;
        __syncthreads();
        #pragma unroll
        for (int fr = 0; fr < 2; fr++)
            #pragma unroll
            for (int fc = 0; fc < 4; fc++)
                wmma::load_matrix_sync(acc[fr][fc], &fs[wc * 64 + fc * 16], 136,
                                       wmma::mem_row_major);
        __syncthreads();
    }

    // ---- async loader geometry (each thread: 2 A-chunks + 2 B-chunks of 16B) -
    const int arow  = tid >> 2;          // 0..63
    const int apart = (tid & 3) * 8;     // element offset within 32-elem row
    const int brow  = tid >> 4;          // 0..15
    const int bpart = (tid & 15) * 8;
    const __nv_bfloat16* Ag0 = A + (size_t)(bm + arow) * K + apart;
    const __nv_bfloat16* Ag1 = A + (size_t)(bm + arow + 64) * K + apart;
    const __nv_bfloat16* Wg0 = W + (size_t)brow * N + bn + bpart;
    const __nv_bfloat16* Wg1 = W + (size_t)(brow + 16) * N + bn + bpart;

#define GEMM_ISSUE(buf, k0)                                                     \
    do {                                                                        \
        cp16(&As[buf][arow * LDA + apart],        Ag0 + (k0));                  \
        cp16(&As[buf][(arow + 64) * LDA + apart], Ag1 + (k0));                  \
        cp16(&Bs[buf][brow * LDB + bpart],        Wg0 + (size_t)(k0) * N);      \
        cp16(&Bs[buf][(brow + 16) * LDB + bpart], Wg1 + (size_t)(k0) * N);      \
        asm volatile("cp.async.commit_group;\n");                               \
    } while (0)

    const int NS = K / BK;
    GEMM_ISSUE(0, 0);

    for (int s = 0; s < NS; s++) {
        if (s + 1 < NS) {
            GEMM_ISSUE((s + 1) & 1, (s + 1) * BK);
            asm volatile("cp.async.wait_group 1;\n");
        } else {
            asm volatile("cp.async.wait_group 0;\n");
        }
        __syncthreads();

        const __nv_bfloat16* as = As[s & 1];
        const __nv_bfloat16* bs = Bs[s & 1];
        #pragma unroll
        for (int kk = 0; kk < BK; kk += 16) {
            wmma::fragment<wmma::matrix_a, 16, 16, 16, __nv_bfloat16,
                           wmma::row_major> af[2];
            wmma::fragment<wmma::matrix_b, 16, 16, 16, __nv_bfloat16,
                           wmma::row_major> bf[4];
            #pragma unroll
            for (int fr = 0; fr < 2; fr++)
                wmma::load_matrix_sync(af[fr], &as[(wr * 32 + fr * 16) * LDA + kk], LDA);
            #pragma unroll
            for (int fc = 0; fc < 4; fc++)
                wmma::load_matrix_sync(bf[fc], &bs[kk * LDB + wc * 64 + fc * 16], LDB);
            #pragma unroll
            for (int fr = 0; fr < 2; fr++)
                #pragma unroll
                for (int fc = 0; fc < 4; fc++)
                    wmma::mma_sync(acc[fr][fc], af[fr], bf[fc], acc[fr][fc]);
        }
        __syncthreads();
    }
#undef GEMM_ISSUE

    #pragma unroll
    for (int fr = 0; fr < 2; fr++)
        #pragma unroll
        for (int fc = 0; fc < 4; fc++) {
            if (RELU) {
                #pragma unroll
                for (int e = 0; e < acc[fr][fc].num_elements; e++)
                    acc[fr][fc].x[e] = fmaxf(acc[fr][fc].x[e], 0.0f);
            }
            float* cp = C + (size_t)(bm + wr * 32 + fr * 16) * N + bn + wc * 64 + fc * 16;
            wmma::store_matrix_sync(cp, acc[fr][fc], N, wmma::mem_row_major);
        }
}

// ============== tensor-core flash attention (tf32 mma.sync, dk=64) ============
#define FLDK 68
#define FLDV 72
#define FLDP 68
#define FKS_OFF 0
#define FVS_OFF (64 * FLDK)
#define FPS_OFF (FVS_OFF + 64 * FLDV)
#define FSMEM_FLOATS (FPS_OFF + 128 * FLDP)
#define FSMEM_BYTES  (FSMEM_FLOATS * 4)

__device__ __forceinline__ unsigned f2tf(float x) {
    unsigned u;
    asm("cvt.rna.tf32.f32 %0, %1;" : "=r"(u) : "f"(x));
    return u;
}

__device__ __forceinline__ void mma_tf32(float* d, const unsigned* a,
                                         const unsigned* b) {
    asm volatile(
        "mma.sync.aligned.m16n8k8.row.col.f32.tf32.tf32.f32 "
        "{%0,%1,%2,%3}, {%4,%5,%6,%7}, {%8,%9}, {%0,%1,%2,%3};\n"
        : "+f"(d[0]), "+f"(d[1]), "+f"(d[2]), "+f"(d[3])
        : "r"(a[0]), "r"(a[1]), "r"(a[2]), "r"(a[3]), "r"(b[0]), "r"(b[1]));
}

__global__ __launch_bounds__(256) void flash_attn_tc(
    const float* __restrict__ Qg, const float* __restrict__ Kg,
    const float* __restrict__ Vg, float* __restrict__ Og,
    int Sq, int Skv)
{
    extern __shared__ float fsm[];
    unsigned* smu = reinterpret_cast<unsigned*>(fsm);

    const int tid  = threadIdx.x;
    const int lane = tid & 31;
    const int w    = tid >> 5;
    const int q0   = blockIdx.x * 128;
    const int h    = blockIdx.y;
    const int b    = blockIdx.z;
    const int r0   = lane >> 2;
    const int cq   = lane & 3;
    const float scale = 0.125f;

    unsigned qa[8][4];
    {
        const float* Qb = Qg + (size_t)(b * Sq + q0 + w * 16) * DMODEL + h * DKH;
        #pragma unroll
        for (int ds = 0; ds < 8; ds++) {
            int c = ds * 8 + cq;
            qa[ds][0] = f2tf(scale * Qb[(size_t)r0       * DMODEL + c]);
            qa[ds][1] = f2tf(scale * Qb[(size_t)(r0 + 8) * DMODEL + c]);
            qa[ds][2] = f2tf(scale * Qb[(size_t)r0       * DMODEL + c + 4]);
            qa[ds][3] = f2tf(scale * Qb[(size_t)(r0 + 8) * DMODEL + c + 4]);
        }
    }

    float m0 = -1e30f, m1 = -1e30f, l0 = 0.0f, l1 = 0.0f;
    float o[8][4];
    #pragma unroll
    for (int nt = 0; nt < 8; nt++)
        o[nt][0] = o[nt][1] = o[nt][2] = o[nt][3] = 0.0f;

    unsigned* const pbase = smu + FPS_OFF + (w * 16) * FLDP;

    for (int kv0 = 0; kv0 < Skv; kv0 += 64) {
        __syncthreads();
        #pragma unroll
        for (int i = 0; i < 4; i++) {
            int idx = tid + 256 * i;
            int r   = idx >> 4;
            int c4  = (idx & 15) << 2;
            size_t gb = (size_t)(b * Skv + kv0 + r) * DMODEL + h * DKH + c4;
            float4 k4 = *reinterpret_cast<const float4*>(Kg + gb);
            float4 v4 = *reinterpret_cast<const float4*>(Vg + gb);
            unsigned* kd = smu + FKS_OFF + r * FLDK + c4;
            kd[0] = f2tf(k4.x); kd[1] = f2tf(k4.y);
            kd[2] = f2tf(k4.z); kd[3] = f2tf(k4.w);
            unsigned* vd = smu + FVS_OFF + r * FLDV + c4;
            vd[0] = f2tf(v4.x); vd[1] = f2tf(v4.y);
            vd[2] = f2tf(v4.z); vd[3] = f2tf(v4.w);
        }
        __syncthreads();

        float s[8][4];
        #pragma unroll
        for (int nt = 0; nt < 8; nt++)
            s[nt][0] = s[nt][1] = s[nt][2] = s[nt][3] = 0.0f;

        #pragma unroll
        for (int ds = 0; ds < 8; ds++) {
            #pragma unroll
            for (int nt = 0; nt < 8; nt++) {
                const unsigned* kp = smu + FKS_OFF + (nt * 8 + r0) * FLDK + ds * 8 + cq;
                unsigned bb[2] = { kp[0], kp[4] };
                mma_tf32(s[nt], qa[ds], bb);
            }
        }

        float mx0 = s[0][0], mx1 = s[0][2];
        #pragma unroll
        for (int nt = 0; nt < 8; nt++) {
            mx0 = fmaxf(mx0, fmaxf(s[nt][0], s[nt][1]));
            mx1 = fmaxf(mx1, fmaxf(s[nt][2], s[nt][3]));
        }
        mx0 = fmaxf(mx0, __shfl_xor_sync(0xffffffffu, mx0, 1));
        mx0 = fmaxf(mx0, __shfl_xor_sync(0xffffffffu, mx0, 2));
        mx1 = fmaxf(mx1, __shfl_xor_sync(0xffffffffu, mx1, 1));
        mx1 = fmaxf(mx1, __shfl_xor_sync(0xffffffffu, mx1, 2));

        float mn0 = fmaxf(m0, mx0), mn1 = fmaxf(m1, mx1);
        float al0 = __expf(m0 - mn0), al1 = __expf(m1 - mn1);
        m0 = mn0; m1 = mn1;

        float sum0 = 0.0f, sum1 = 0.0f;
        #pragma unroll
        for (int nt = 0; nt < 8; nt++) {
            s[nt][0] = __expf(s[nt][0] - mn0);
            s[nt][1] = __expf(s[nt][1] - mn0);
            s[nt][2] = __expf(s[nt][2] - mn1);
            s[nt][3] = __expf(s[nt][3] - mn1);
            sum0 += s[nt][0] + s[nt][1];
            sum1 += s[nt][2] + s[nt][3];
        }
        sum0 += __shfl_xor_sync(0xffffffffu, sum0, 1);
        sum0 += __shfl_xor_sync(0xffffffffu, sum0, 2);
        sum1 += __shfl_xor_sync(0xffffffffu, sum1, 1);
        sum1 += __shfl_xor_sync(0xffffffffu, sum1, 2);
        l0 = l0 * al0 + sum0;
        l1 = l1 * al1 + sum1;

        #pragma unroll
        for (int nt = 0; nt < 8; nt++) {
            o[nt][0] *= al0; o[nt][1] *= al0;
            o[nt][2] *= al1; o[nt][3] *= al1;
            uint2 p01 = make_uint2(f2tf(s[nt][0]), f2tf(s[nt][1]));
            uint2 p23 = make_uint2(f2tf(s[nt][2]), f2tf(s[nt][3]));
            *reinterpret_cast<uint2*>(pbase + r0 * FLDP + nt * 8 + 2 * cq)       = p01;
            *reinterpret_cast<uint2*>(pbase + (r0 + 8) * FLDP + nt * 8 + 2 * cq) = p23;
        }
        __syncwarp();

        #pragma unroll
        for (int kk = 0; kk < 8; kk++) {
            const unsigned* pp = pbase + r0 * FLDP + kk * 8 + cq;
            unsigned pa[4];
            pa[0] = pp[0];
            pa[1] = pp[8 * FLDP];
            pa[2] = pp[4];
            pa[3] = pp[8 * FLDP + 4];
            #pragma unroll
            for (int nt = 0; nt < 8; nt++) {
                const unsigned* vp = smu + FVS_OFF + (kk * 8 + cq) * FLDV + nt * 8 + r0;
                unsigned bb[2] = { vp[0], vp[4 * FLDV] };
                mma_tf32(o[nt], pa, bb);
            }
        }
    }

    const float i0 = 1.0f / l0, i1 = 1.0f / l1;
    float* Ob = Og + (size_t)(b * Sq + q0 + w * 16) * DMODEL + h * DKH;
    #pragma unroll
    for (int nt = 0; nt < 8; nt++) {
        float2 v0 = make_float2(o[nt][0] * i0, o[nt][1] * i0);
        float2 v1 = make_float2(o[nt][2] * i1, o[nt][3] * i1);
        *reinterpret_cast<float2*>(Ob + (size_t)r0 * DMODEL + nt * 8 + 2 * cq)       = v0;
        *reinterpret_cast<float2*>(Ob + (size_t)(r0 + 8) * DMODEL + nt * 8 + 2 * cq) = v1;
    }
}

// ---------------- out = LayerNorm(a + c) * g + b ------------------------------
__global__ __launch_bounds__(256) void add_ln_kernel(
    const float* __restrict__ a, const float* __restrict__ cadd,
    const float* __restrict__ g, const float* __restrict__ be,
    float* __restrict__ out)
{
    __shared__ float red[16];
    const int row = blockIdx.x;
    const int tid = threadIdx.x;
    const size_t base = (size_t)row * DMODEL + tid * 4;

    float4 av = *reinterpret_cast<const float4*>(a + base);
    float4 cv = *reinterpret_cast<const float4*>(cadd + base);
    float x0 = av.x + cv.x, x1 = av.y + cv.y;
    float x2 = av.z + cv.z, x3 = av.w + cv.w;

    float s  = x0 + x1 + x2 + x3;
    float ss = x0 * x0 + x1 * x1 + x2 * x2 + x3 * x3;
    #pragma unroll
    for (int off = 16; off; off >>= 1) {
        s  += __shfl_xor_sync(0xffffffffu, s,  off);
        ss += __shfl_xor_sync(0xffffffffu, ss, off);
    }
    if ((tid & 31) == 0) { red[tid >> 5] = s; red[8 + (tid >> 5)] = ss; }
    __syncthreads();
    float ts = 0.0f, tss = 0.0f;
    #pragma unroll
    for (int i = 0; i < 8; i++) { ts += red[i]; tss += red[8 + i]; }

    const float mu  = ts * (1.0f / DMODEL);
    const float var = tss * (1.0f / DMODEL) - mu * mu;
    const float inv = rsqrtf(var + 1e-5f);

    float4 gv = *reinterpret_cast<const float4*>(g  + tid * 4);
    float4 bv = *reinterpret_cast<const float4*>(be + tid * 4);
    float4 ov;
    ov.x = (x0 - mu) * inv * gv.x + bv.x;
    ov.y = (x1 - mu) * inv * gv.y + bv.y;
    ov.z = (x2 - mu) * inv * gv.z + bv.z;
    ov.w = (x3 - mu) * inv * gv.w + bv.w;
    *reinterpret_cast<float4*>(out + base) = ov;
}

// ------------------------------- host driver ----------------------------------
static inline void conv_f2bf(const float* in, __nv_bfloat16* out, int n) {
    int n4 = n >> 2;
    f2bf_kernel<<<(n4 + 255) / 256, 256>>>(in, out, n4);
}

static inline void launch_gemm16(const __nv_bfloat16* A, const __nv_bfloat16* W,
                                 const float* B, float* C,
                                 int M, int N, int K, int relu)
{
    dim3 grid(N / 128, M / 128), blk(256);
    if (relu) bf16_gemm_bias<1><<<grid, blk>>>(A, W, B, C, M, N, K);
    else      bf16_gemm_bias<0><<<grid, blk>>>(A, W, B, C, M, N, K);
}

extern "C" void kernel_launch(void* const* d_in, const int* in_sizes, int n_in,
                              void* d_out, int out_size)
{
    const float* src   = (const float*)d_in[0];
    const float* tgt   = (const float*)d_in[1];
    const float* sa_wq = (const float*)d_in[2];
    const float* sa_bq = (const float*)d_in[3];
    const float* sa_wk = (const float*)d_in[4];
    const float* sa_bk = (const float*)d_in[5];
    const float* sa_wv = (const float*)d_in[6];
    const float* sa_bv = (const float*)d_in[7];
    const float* sa_wo = (const float*)d_in[8];
    const float* sa_bo = (const float*)d_in[9];
    const float* ca_wq = (const float*)d_in[10];
    const float* ca_bq = (const float*)d_in[11];
    const float* ca_wk = (const float*)d_in[12];
    const float* ca_bk = (const float*)d_in[13];
    const float* ca_wv = (const float*)d_in[14];
    const float* ca_bv = (const float*)d_in[15];
    const float* ca_wo = (const float*)d_in[16];
    const float* ca_bo = (const float*)d_in[17];
    const float* ff_w1 = (const float*)d_in[18];
    const float* ff_b1 = (const float*)d_in[19];
    const float* ff_w2 = (const float*)d_in[20];
    const float* ff_b2 = (const float*)d_in[21];
    const float* ln1_g = (const float*)d_in[22];
    const float* ln1_b = (const float*)d_in[23];
    const float* ln2_g = (const float*)d_in[24];
    const float* ln2_b = (const float*)d_in[25];
    const float* ln3_g = (const float*)d_in[26];
    const float* ln3_b = (const float*)d_in[27];
    float* out = (float*)d_out;

    float *q, *k, *v, *attn, *x1, *x2, *t, *h;
    __nv_bfloat16 *a16, *w16;
    cudaGetSymbolAddress((void**)&q,    g_q);
    cudaGetSymbolAddress((void**)&k,    g_k);
    cudaGetSymbolAddress((void**)&v,    g_v);
    cudaGetSymbolAddress((void**)&attn, g_attn);
    cudaGetSymbolAddress((void**)&x1,   g_x1);
    cudaGetSymbolAddress((void**)&x2,   g_x2);
    cudaGetSymbolAddress((void**)&t,    g_t);
    cudaGetSymbolAddress((void**)&h,    g_h);
    cudaGetSymbolAddress((void**)&a16,  g_a16);
    cudaGetSymbolAddress((void**)&w16,  g_w16);

    cudaFuncSetAttribute(flash_attn_tc,
                         cudaFuncAttributeMaxDynamicSharedMemorySize, FSMEM_BYTES);

    dim3 fgrid(SEQ / 128, NHEAD, BATCH), blk(256);
    const int NMM = MTOK * DMODEL;      // 8M activation elements
    const int NW  = DMODEL * DMODEL;    // 1M weight elements

    // ---- self-attention block ----
    conv_f2bf(tgt, a16, NMM);
    conv_f2bf(sa_wq, w16, NW);
    launch_gemm16(a16, w16, sa_bq, q, MTOK, DMODEL, DMODEL, 0);
    conv_f2bf(sa_wk, w16, NW);
    launch_gemm16(a16, w16, sa_bk, k, MTOK, DMODEL, DMODEL, 0);
    conv_f2bf(sa_wv, w16, NW);
    launch_gemm16(a16, w16, sa_bv, v, MTOK, DMODEL, DMODEL, 0);
    flash_attn_tc<<<fgrid, blk, FSMEM_BYTES>>>(q, k, v, attn, SEQ, SEQ);
    conv_f2bf(attn, a16, NMM);
    conv_f2bf(sa_wo, w16, NW);
    launch_gemm16(a16, w16, sa_bo, t, MTOK, DMODEL, DMODEL, 0);
    add_ln_kernel<<<MTOK, blk>>>(tgt, t, ln1_g, ln1_b, x1);

    // ---- cross-attention block ----
    conv_f2bf(x1, a16, NMM);
    conv_f2bf(ca_wq, w16, NW);
    launch_gemm16(a16, w16, ca_bq, q, MTOK, DMODEL, DMODEL, 0);
    conv_f2bf(src, a16, NMM);
    conv_f2bf(ca_wk, w16, NW);
    launch_gemm16(a16, w16, ca_bk, k, MTOK, DMODEL, DMODEL, 0);
    conv_f2bf(ca_wv, w16, NW);
    launch_gemm16(a16, w16, ca_bv, v, MTOK, DMODEL, DMODEL, 0);
    flash_attn_tc<<<fgrid, blk, FSMEM_BYTES>>>(q, k, v, attn, SEQ, SEQ);
    conv_f2bf(attn, a16, NMM);
    conv_f2bf(ca_wo, w16, NW);
    launch_gemm16(a16, w16, ca_bo, t, MTOK, DMODEL, DMODEL, 0);
    add_ln_kernel<<<MTOK, blk>>>(x1, t, ln2_g, ln2_b, x2);

    // ---- feed-forward block ----
    conv_f2bf(x2, a16, NMM);
    conv_f2bf(ff_w1, w16, DMODEL * DFF);
    launch_gemm16(a16, w16, ff_b1, h, MTOK, DFF, DMODEL, 1);
    conv_f2bf(h, a16, MTOK * DFF);
    conv_f2bf(ff_w2, w16, DFF * DMODEL);
    launch_gemm16(a16, w16, ff_b2, t, MTOK, DMODEL, DFF, 0);
    add_ln_kernel<<<MTOK, blk>>>(x2, t, ln3_g, ln3_b, out);
}

// round 9
// speedup vs baseline: 3.2195x; 1.5767x over previous
#include <cuda_runtime.h>
#include <cuda_bf16.h>
#include <mma.h>

using namespace nvcuda;

#define DMODEL 1024
#define NHEAD  16
#define DKH    64
#define DFF    4096
#define BATCH  4
#define SEQ    2048
#define MTOK   (BATCH * SEQ)

// ---------------- scratch (device globals; no allocation allowed) -------------
__device__ float g_q[MTOK * DMODEL];
__device__ float g_k[MTOK * DMODEL];
__device__ float g_v[MTOK * DMODEL];
__device__ float g_attn[MTOK * DMODEL];
__device__ float g_x1[MTOK * DMODEL];
__device__ float g_x2[MTOK * DMODEL];
__device__ float g_t[MTOK * DMODEL];
__device__ float g_h[MTOK * DFF];
__device__ __nv_bfloat16 g_a16[MTOK * DFF];     // bf16 A-operand scratch
__device__ __nv_bfloat16 g_w16[DMODEL * DFF];   // bf16 W-operand scratch

// ---------------- fp32 -> bf16 conversion (vectorized) ------------------------
__global__ __launch_bounds__(256) void f2bf_kernel(
    const float* __restrict__ in, __nv_bfloat16* __restrict__ out, int n4)
{
    int i = blockIdx.x * blockDim.x + threadIdx.x;
    if (i < n4) {
        float4 v = reinterpret_cast<const float4*>(in)[i];
        __nv_bfloat162 a = __floats2bfloat162_rn(v.x, v.y);
        __nv_bfloat162 b = __floats2bfloat162_rn(v.z, v.w);
        uint2 u;
        u.x = *reinterpret_cast<unsigned*>(&a);
        u.y = *reinterpret_cast<unsigned*>(&b);
        reinterpret_cast<uint2*>(out)[i] = u;
    }
}

// ---------------- cp.async helper ---------------------------------------------
__device__ __forceinline__ void cp16(void* dst, const void* src) {
    unsigned d = (unsigned)__cvta_generic_to_shared(dst);
    asm volatile("cp.async.cg.shared.global [%0], [%1], 16;\n" :: "r"(d), "l"(src));
}

// ---------------- bf16 WMMA GEMM: C = A(MxK) @ W(KxN) + bias, optional ReLU ---
// BM=256, BN=128, BK=32; 8 warps, warp tile 64x64 (4x4 m16n16k16 frags).
// 3-stage cp.async ring in dynamic smem. A,W bf16 row-major; bias/out fp32.
template <int RELU>
__global__ __launch_bounds__(256) void bf16_gemm_bias(
    const __nv_bfloat16* __restrict__ A, const __nv_bfloat16* __restrict__ W,
    const float* __restrict__ bias, float* __restrict__ C,
    int M, int N, int K)
{
    constexpr int BM = 256, BN = 128, BK = 32;
    constexpr int LDA = 40;            // row stride 80B (16B multiple)
    constexpr int LDB = 136;           // row stride 272B (16B multiple)
    constexpr int ASTG = BM * LDA;     // 10240 elems per stage
    constexpr int BSTG = BK * LDB;     // 4352 elems per stage
    extern __shared__ __nv_bfloat16 gs[];
    __nv_bfloat16* const Asm = gs;
    __nv_bfloat16* const Bsm = gs + 3 * ASTG;

    const int tid = threadIdx.x;
    const int wid = tid >> 5;
    const int wm  = wid >> 1;    // 0..3 -> M offset wm*64
    const int wn  = wid & 1;     // 0..1 -> N offset wn*64
    const int bm  = blockIdx.y * BM;
    const int bn  = blockIdx.x * BN;

    wmma::fragment<wmma::accumulator, 16, 16, 16, float> acc[4][4];

    // ---- init accumulators from bias (fp32 staging in smem start) ------------
    {
        float* fs = reinterpret_cast<float*>(gs);
        int rr = tid >> 5;               // 0..7
        int n4 = (tid & 31) << 2;        // 0..124
        float4 bv = *reinterpret_cast<const float4*>(bias + bn + n4);
        *reinterpret_cast<float4*>(&fs[rr * 136 + n4])       = bv;
        *reinterpret_cast<float4*>(&fs[(rr + 8) * 136 + n4]) = bv;
        __syncthreads();
        #pragma unroll
        for (int fc = 0; fc < 4; fc++) {
            wmma::load_matrix_sync(acc[0][fc], &fs[wn * 64 + fc * 16], 136,
                                   wmma::mem_row_major);
            #pragma unroll
            for (int fr = 1; fr < 4; fr++)
                #pragma unroll
                for (int e = 0; e < acc[0][fc].num_elements; e++)
                    acc[fr][fc].x[e] = acc[0][fc].x[e];
        }
        __syncthreads();
    }

    // ---- async loader geometry: 4 A-chunks + 2 B-chunks of 16B per thread ----
    const int arow  = tid >> 2;          // 0..63
    const int apart = (tid & 3) * 8;     // 0,8,16,24
    const int brow  = tid >> 4;          // 0..15
    const int bpart = (tid & 15) * 8;    // 0..120
    const __nv_bfloat16* const Ab = A + (size_t)bm * K;
    const __nv_bfloat16* const Wb = W + bn;

#define GISS(st, k0)                                                             \
    do {                                                                         \
        __nv_bfloat16* as = Asm + (st) * ASTG;                                   \
        __nv_bfloat16* bs = Bsm + (st) * BSTG;                                   \
        cp16(&as[(arow      ) * LDA + apart], Ab + (size_t)(arow      ) * K + (k0) + apart); \
        cp16(&as[(arow +  64) * LDA + apart], Ab + (size_t)(arow +  64) * K + (k0) + apart); \
        cp16(&as[(arow + 128) * LDA + apart], Ab + (size_t)(arow + 128) * K + (k0) + apart); \
        cp16(&as[(arow + 192) * LDA + apart], Ab + (size_t)(arow + 192) * K + (k0) + apart); \
        cp16(&bs[(brow     ) * LDB + bpart], Wb + (size_t)((k0) + brow     ) * N + bpart);   \
        cp16(&bs[(brow + 16) * LDB + bpart], Wb + (size_t)((k0) + brow + 16) * N + bpart);   \
        asm volatile("cp.async.commit_group;\n");                                \
    } while (0)

    const int NS = K / BK;
    GISS(0, 0);
    if (NS > 1) GISS(1, BK);

    int st = 0;
    for (int s = 0; s < NS; s++) {
        asm volatile("cp.async.wait_group 1;\n");
        __syncthreads();   // stage s visible; stage (s-1)'s buffer now reusable

        const __nv_bfloat16* as = Asm + st * ASTG;
        const __nv_bfloat16* bs = Bsm + st * BSTG;
        #pragma unroll
        for (int kk = 0; kk < BK; kk += 16) {
            wmma::fragment<wmma::matrix_a, 16, 16, 16, __nv_bfloat16,
                           wmma::row_major> af[4];
            wmma::fragment<wmma::matrix_b, 16, 16, 16, __nv_bfloat16,
                           wmma::row_major> bf[4];
            #pragma unroll
            for (int fr = 0; fr < 4; fr++)
                wmma::load_matrix_sync(af[fr], &as[(wm * 64 + fr * 16) * LDA + kk], LDA);
            #pragma unroll
            for (int fc = 0; fc < 4; fc++)
                wmma::load_matrix_sync(bf[fc], &bs[kk * LDB + wn * 64 + fc * 16], LDB);
            #pragma unroll
            for (int fr = 0; fr < 4; fr++)
                #pragma unroll
                for (int fc = 0; fc < 4; fc++)
                    wmma::mma_sync(acc[fr][fc], af[fr], bf[fc], acc[fr][fc]);
        }

        if (s + 2 < NS) {
            int nst = (st + 2) % 3;   // buffer consumed in iteration s-1
            GISS(nst, (s + 2) * BK);
        }
        st = (st + 1) % 3;
    }
#undef GISS

    #pragma unroll
    for (int fr = 0; fr < 4; fr++)
        #pragma unroll
        for (int fc = 0; fc < 4; fc++) {
            if (RELU) {
                #pragma unroll
                for (int e = 0; e < acc[fr][fc].num_elements; e++)
                    acc[fr][fc].x[e] = fmaxf(acc[fr][fc].x[e], 0.0f);
            }
            float* cp = C + (size_t)(bm + wm * 64 + fr * 16) * N + bn + wn * 64 + fc * 16;
            wmma::store_matrix_sync(cp, acc[fr][fc], N, wmma::mem_row_major);
        }
}

#define GSMEM_BYTES ((3 * (256 * 40) + 3 * (32 * 136)) * 2)   // 87552

// ============== tensor-core flash attention (tf32 mma.sync, dk=64) ============
#define FLDK 68
#define FLDV 72
#define FLDP 68
#define FKS_OFF 0
#define FVS_OFF (64 * FLDK)
#define FPS_OFF (FVS_OFF + 64 * FLDV)
#define FSMEM_FLOATS (FPS_OFF + 128 * FLDP)
#define FSMEM_BYTES  (FSMEM_FLOATS * 4)

__device__ __forceinline__ unsigned f2tf(float x) {
    unsigned u;
    asm("cvt.rna.tf32.f32 %0, %1;" : "=r"(u) : "f"(x));
    return u;
}

__device__ __forceinline__ void mma_tf32(float* d, const unsigned* a,
                                         const unsigned* b) {
    asm volatile(
        "mma.sync.aligned.m16n8k8.row.col.f32.tf32.tf32.f32 "
        "{%0,%1,%2,%3}, {%4,%5,%6,%7}, {%8,%9}, {%0,%1,%2,%3};\n"
        : "+f"(d[0]), "+f"(d[1]), "+f"(d[2]), "+f"(d[3])
        : "r"(a[0]), "r"(a[1]), "r"(a[2]), "r"(a[3]), "r"(b[0]), "r"(b[1]));
}

__global__ __launch_bounds__(256) void flash_attn_tc(
    const float* __restrict__ Qg, const float* __restrict__ Kg,
    const float* __restrict__ Vg, float* __restrict__ Og,
    int Sq, int Skv)
{
    extern __shared__ float fsm[];
    unsigned* smu = reinterpret_cast<unsigned*>(fsm);

    const int tid  = threadIdx.x;
    const int lane = tid & 31;
    const int w    = tid >> 5;
    const int q0   = blockIdx.x * 128;
    const int h    = blockIdx.y;
    const int b    = blockIdx.z;
    const int r0   = lane >> 2;
    const int cq   = lane & 3;
    const float scale = 0.125f;

    unsigned qa[8][4];
    {
        const float* Qb = Qg + (size_t)(b * Sq + q0 + w * 16) * DMODEL + h * DKH;
        #pragma unroll
        for (int ds = 0; ds < 8; ds++) {
            int c = ds * 8 + cq;
            qa[ds][0] = f2tf(scale * Qb[(size_t)r0       * DMODEL + c]);
            qa[ds][1] = f2tf(scale * Qb[(size_t)(r0 + 8) * DMODEL + c]);
            qa[ds][2] = f2tf(scale * Qb[(size_t)r0       * DMODEL + c + 4]);
            qa[ds][3] = f2tf(scale * Qb[(size_t)(r0 + 8) * DMODEL + c + 4]);
        }
    }

    float m0 = -1e30f, m1 = -1e30f, l0 = 0.0f, l1 = 0.0f;
    float o[8][4];
    #pragma unroll
    for (int nt = 0; nt < 8; nt++)
        o[nt][0] = o[nt][1] = o[nt][2] = o[nt][3] = 0.0f;

    unsigned* const pbase = smu + FPS_OFF + (w * 16) * FLDP;

    for (int kv0 = 0; kv0 < Skv; kv0 += 64) {
        __syncthreads();
        #pragma unroll
        for (int i = 0; i < 4; i++) {
            int idx = tid + 256 * i;
            int r   = idx >> 4;
            int c4  = (idx & 15) << 2;
            size_t gb = (size_t)(b * Skv + kv0 + r) * DMODEL + h * DKH + c4;
            float4 k4 = *reinterpret_cast<const float4*>(Kg + gb);
            float4 v4 = *reinterpret_cast<const float4*>(Vg + gb);
            unsigned* kd = smu + FKS_OFF + r * FLDK + c4;
            kd[0] = f2tf(k4.x); kd[1] = f2tf(k4.y);
            kd[2] = f2tf(k4.z); kd[3] = f2tf(k4.w);
            unsigned* vd = smu + FVS_OFF + r * FLDV + c4;
            vd[0] = f2tf(v4.x); vd[1] = f2tf(v4.y);
            vd[2] = f2tf(v4.z); vd[3] = f2tf(v4.w);
        }
        __syncthreads();

        float s[8][4];
        #pragma unroll
        for (int nt = 0; nt < 8; nt++)
            s[nt][0] = s[nt][1] = s[nt][2] = s[nt][3] = 0.0f;

        #pragma unroll
        for (int ds = 0; ds < 8; ds++) {
            #pragma unroll
            for (int nt = 0; nt < 8; nt++) {
                const unsigned* kp = smu + FKS_OFF + (nt * 8 + r0) * FLDK + ds * 8 + cq;
                unsigned bb[2] = { kp[0], kp[4] };
                mma_tf32(s[nt], qa[ds], bb);
            }
        }

        float mx0 = s[0][0], mx1 = s[0][2];
        #pragma unroll
        for (int nt = 0; nt < 8; nt++) {
            mx0 = fmaxf(mx0, fmaxf(s[nt][0], s[nt][1]));
            mx1 = fmaxf(mx1, fmaxf(s[nt][2], s[nt][3]));
        }
        mx0 = fmaxf(mx0, __shfl_xor_sync(0xffffffffu, mx0, 1));
        mx0 = fmaxf(mx0, __shfl_xor_sync(0xffffffffu, mx0, 2));
        mx1 = fmaxf(mx1, __shfl_xor_sync(0xffffffffu, mx1, 1));
        mx1 = fmaxf(mx1, __shfl_xor_sync(0xffffffffu, mx1, 2));

        float mn0 = fmaxf(m0, mx0), mn1 = fmaxf(m1, mx1);
        float al0 = __expf(m0 - mn0), al1 = __expf(m1 - mn1);
        m0 = mn0; m1 = mn1;

        float sum0 = 0.0f, sum1 = 0.0f;
        #pragma unroll
        for (int nt = 0; nt < 8; nt++) {
            s[nt][0] = __expf(s[nt][0] - mn0);
            s[nt][1] = __expf(s[nt][1] - mn0);
            s[nt][2] = __expf(s[nt][2] - mn1);
            s[nt][3] = __expf(s[nt][3] - mn1);
            sum0 += s[nt][0] + s[nt][1];
            sum1 += s[nt][2] + s[nt][3];
        }
        sum0 += __shfl_xor_sync(0xffffffffu, sum0, 1);
        sum0 += __shfl_xor_sync(0xffffffffu, sum0, 2);
        sum1 += __shfl_xor_sync(0xffffffffu, sum1, 1);
        sum1 += __shfl_xor_sync(0xffffffffu, sum1, 2);
        l0 = l0 * al0 + sum0;
        l1 = l1 * al1 + sum1;

        #pragma unroll
        for (int nt = 0; nt < 8; nt++) {
            o[nt][0] *= al0; o[nt][1] *= al0;
            o[nt][2] *= al1; o[nt][3] *= al1;
            uint2 p01 = make_uint2(f2tf(s[nt][0]), f2tf(s[nt][1]));
            uint2 p23 = make_uint2(f2tf(s[nt][2]), f2tf(s[nt][3]));
            *reinterpret_cast<uint2*>(pbase + r0 * FLDP + nt * 8 + 2 * cq)       = p01;
            *reinterpret_cast<uint2*>(pbase + (r0 + 8) * FLDP + nt * 8 + 2 * cq) = p23;
        }
        __syncwarp();

        #pragma unroll
        for (int kk = 0; kk < 8; kk++) {
            const unsigned* pp = pbase + r0 * FLDP + kk * 8 + cq;
            unsigned pa[4];
            pa[0] = pp[0];
            pa[1] = pp[8 * FLDP];
            pa[2] = pp[4];
            pa[3] = pp[8 * FLDP + 4];
            #pragma unroll
            for (int nt = 0; nt < 8; nt++) {
                const unsigned* vp = smu + FVS_OFF + (kk * 8 + cq) * FLDV + nt * 8 + r0;
                unsigned bb[2] = { vp[0], vp[4 * FLDV] };
                mma_tf32(o[nt], pa, bb);
            }
        }
    }

    const float i0 = 1.0f / l0, i1 = 1.0f / l1;
    float* Ob = Og + (size_t)(b * Sq + q0 + w * 16) * DMODEL + h * DKH;
    #pragma unroll
    for (int nt = 0; nt < 8; nt++) {
        float2 v0 = make_float2(o[nt][0] * i0, o[nt][1] * i0);
        float2 v1 = make_float2(o[nt][2] * i1, o[nt][3] * i1);
        *reinterpret_cast<float2*>(Ob + (size_t)r0 * DMODEL + nt * 8 + 2 * cq)       = v0;
        *reinterpret_cast<float2*>(Ob + (size_t)(r0 + 8) * DMODEL + nt * 8 + 2 * cq) = v1;
    }
}

// ---------------- out = LayerNorm(a + c) * g + b ------------------------------
__global__ __launch_bounds__(256) void add_ln_kernel(
    const float* __restrict__ a, const float* __restrict__ cadd,
    const float* __restrict__ g, const float* __restrict__ be,
    float* __restrict__ out)
{
    __shared__ float red[16];
    const int row = blockIdx.x;
    const int tid = threadIdx.x;
    const size_t base = (size_t)row * DMODEL + tid * 4;

    float4 av = *reinterpret_cast<const float4*>(a + base);
    float4 cv = *reinterpret_cast<const float4*>(cadd + base);
    float x0 = av.x + cv.x, x1 = av.y + cv.y;
    float x2 = av.z + cv.z, x3 = av.w + cv.w;

    float s  = x0 + x1 + x2 + x3;
    float ss = x0 * x0 + x1 * x1 + x2 * x2 + x3 * x3;
    #pragma unroll
    for (int off = 16; off; off >>= 1) {
        s  += __shfl_xor_sync(0xffffffffu, s,  off);
        ss += __shfl_xor_sync(0xffffffffu, ss, off);
    }
    if ((tid & 31) == 0) { red[tid >> 5] = s; red[8 + (tid >> 5)] = ss; }
    __syncthreads();
    float ts = 0.0f, tss = 0.0f;
    #pragma unroll
    for (int i = 0; i < 8; i++) { ts += red[i]; tss += red[8 + i]; }

    const float mu  = ts * (1.0f / DMODEL);
    const float var = tss * (1.0f / DMODEL) - mu * mu;
    const float inv = rsqrtf(var + 1e-5f);

    float4 gv = *reinterpret_cast<const float4*>(g  + tid * 4);
    float4 bv = *reinterpret_cast<const float4*>(be + tid * 4);
    float4 ov;
    ov.x = (x0 - mu) * inv * gv.x + bv.x;
    ov.y = (x1 - mu) * inv * gv.y + bv.y;
    ov.z = (x2 - mu) * inv * gv.z + bv.z;
    ov.w = (x3 - mu) * inv * gv.w + bv.w;
    *reinterpret_cast<float4*>(out + base) = ov;
}

// ------------------------------- host driver ----------------------------------
static inline void conv_f2bf(const float* in, __nv_bfloat16* out, int n) {
    int n4 = n >> 2;
    f2bf_kernel<<<(n4 + 255) / 256, 256>>>(in, out, n4);
}

static inline void launch_gemm16(const __nv_bfloat16* A, const __nv_bfloat16* W,
                                 const float* B, float* C,
                                 int M, int N, int K, int relu)
{
    dim3 grid(N / 128, M / 256), blk(256);
    if (relu) bf16_gemm_bias<1><<<grid, blk, GSMEM_BYTES>>>(A, W, B, C, M, N, K);
    else      bf16_gemm_bias<0><<<grid, blk, GSMEM_BYTES>>>(A, W, B, C, M, N, K);
}

extern "C" void kernel_launch(void* const* d_in, const int* in_sizes, int n_in,
                              void* d_out, int out_size)
{
    const float* src   = (const float*)d_in[0];
    const float* tgt   = (const float*)d_in[1];
    const float* sa_wq = (const float*)d_in[2];
    const float* sa_bq = (const float*)d_in[3];
    const float* sa_wk = (const float*)d_in[4];
    const float* sa_bk = (const float*)d_in[5];
    const float* sa_wv = (const float*)d_in[6];
    const float* sa_bv = (const float*)d_in[7];
    const float* sa_wo = (const float*)d_in[8];
    const float* sa_bo = (const float*)d_in[9];
    const float* ca_wq = (const float*)d_in[10];
    const float* ca_bq = (const float*)d_in[11];
    const float* ca_wk = (const float*)d_in[12];
    const float* ca_bk = (const float*)d_in[13];
    const float* ca_wv = (const float*)d_in[14];
    const float* ca_bv = (const float*)d_in[15];
    const float* ca_wo = (const float*)d_in[16];
    const float* ca_bo = (const float*)d_in[17];
    const float* ff_w1 = (const float*)d_in[18];
    const float* ff_b1 = (const float*)d_in[19];
    const float* ff_w2 = (const float*)d_in[20];
    const float* ff_b2 = (const float*)d_in[21];
    const float* ln1_g = (const float*)d_in[22];
    const float* ln1_b = (const float*)d_in[23];
    const float* ln2_g = (const float*)d_in[24];
    const float* ln2_b = (const float*)d_in[25];
    const float* ln3_g = (const float*)d_in[26];
    const float* ln3_b = (const float*)d_in[27];
    float* out = (float*)d_out;

    float *q, *k, *v, *attn, *x1, *x2, *t, *h;
    __nv_bfloat16 *a16, *w16;
    cudaGetSymbolAddress((void**)&q,    g_q);
    cudaGetSymbolAddress((void**)&k,    g_k);
    cudaGetSymbolAddress((void**)&v,    g_v);
    cudaGetSymbolAddress((void**)&attn, g_attn);
    cudaGetSymbolAddress((void**)&x1,   g_x1);
    cudaGetSymbolAddress((void**)&x2,   g_x2);
    cudaGetSymbolAddress((void**)&t,    g_t);
    cudaGetSymbolAddress((void**)&h,    g_h);
    cudaGetSymbolAddress((void**)&a16,  g_a16);
    cudaGetSymbolAddress((void**)&w16,  g_w16);

    cudaFuncSetAttribute(flash_attn_tc,
                         cudaFuncAttributeMaxDynamicSharedMemorySize, FSMEM_BYTES);
    cudaFuncSetAttribute(bf16_gemm_bias<0>,
                         cudaFuncAttributeMaxDynamicSharedMemorySize, GSMEM_BYTES);
    cudaFuncSetAttribute(bf16_gemm_bias<1>,
                         cudaFuncAttributeMaxDynamicSharedMemorySize, GSMEM_BYTES);

    dim3 fgrid(SEQ / 128, NHEAD, BATCH), blk(256);
    const int NMM = MTOK * DMODEL;
    const int NW  = DMODEL * DMODEL;

    // ---- self-attention block ----
    conv_f2bf(tgt, a16, NMM);
    conv_f2bf(sa_wq, w16, NW);
    launch_gemm16(a16, w16, sa_bq, q, MTOK, DMODEL, DMODEL, 0);
    conv_f2bf(sa_wk, w16, NW);
    launch_gemm16(a16, w16, sa_bk, k, MTOK, DMODEL, DMODEL, 0);
    conv_f2bf(sa_wv, w16, NW);
    launch_gemm16(a16, w16, sa_bv, v, MTOK, DMODEL, DMODEL, 0);
    flash_attn_tc<<<fgrid, blk, FSMEM_BYTES>>>(q, k, v, attn, SEQ, SEQ);
    conv_f2bf(attn, a16, NMM);
    conv_f2bf(sa_wo, w16, NW);
    launch_gemm16(a16, w16, sa_bo, t, MTOK, DMODEL, DMODEL, 0);
    add_ln_kernel<<<MTOK, blk>>>(tgt, t, ln1_g, ln1_b, x1);

    // ---- cross-attention block ----
    conv_f2bf(x1, a16, NMM);
    conv_f2bf(ca_wq, w16, NW);
    launch_gemm16(a16, w16, ca_bq, q, MTOK, DMODEL, DMODEL, 0);
    conv_f2bf(src, a16, NMM);
    conv_f2bf(ca_wk, w16, NW);
    launch_gemm16(a16, w16, ca_bk, k, MTOK, DMODEL, DMODEL, 0);
    conv_f2bf(ca_wv, w16, NW);
    launch_gemm16(a16, w16, ca_bv, v, MTOK, DMODEL, DMODEL, 0);
    flash_attn_tc<<<fgrid, blk, FSMEM_BYTES>>>(q, k, v, attn, SEQ, SEQ);
    conv_f2bf(attn, a16, NMM);
    conv_f2bf(ca_wo, w16, NW);
    launch_gemm16(a16, w16, ca_bo, t, MTOK, DMODEL, DMODEL, 0);
    add_ln_kernel<<<MTOK, blk>>>(x1, t, ln2_g, ln2_b, x2);

    // ---- feed-forward block ----
    conv_f2bf(x2, a16, NMM);
    conv_f2bf(ff_w1, w16, DMODEL * DFF);
    launch_gemm16(a16, w16, ff_b1, h, MTOK, DFF, DMODEL, 1);
    conv_f2bf(h, a16, MTOK * DFF);
    conv_f2bf(ff_w2, w16, DFF * DMODEL);
    launch_gemm16(a16, w16, ff_b2, t, MTOK, DMODEL, DFF, 0);
    add_ln_kernel<<<MTOK, blk>>>(x2, t, ln3_g, ln3_b, out);
}

// round 10
// speedup vs baseline: 3.7521x; 1.1654x over previous
#include <cuda_runtime.h>
#include <cuda_bf16.h>
#include <mma.h>

using namespace nvcuda;

#define DMODEL 1024
#define NHEAD  16
#define DKH    64
#define DFF    4096
#define BATCH  4
#define SEQ    2048
#define MTOK   (BATCH * SEQ)

// ---------------- scratch (device globals; no allocation allowed) -------------
__device__ float g_q[MTOK * DMODEL];
__device__ float g_k[MTOK * DMODEL];
__device__ float g_v[MTOK * DMODEL];
__device__ float g_x1[MTOK * DMODEL];
__device__ float g_x2[MTOK * DMODEL];
__device__ float g_t[MTOK * DMODEL];
__device__ __nv_bfloat16 g_a16[2 * MTOK * DMODEL];  // two activation slots
__device__ __nv_bfloat16 g_h16[MTOK * DFF];         // FF hidden (bf16)
__device__ __nv_bfloat16 g_w16[DMODEL * DFF];       // weight scratch

// ---------------- fp32 -> bf16 conversion (vectorized) ------------------------
__global__ __launch_bounds__(256) void f2bf_kernel(
    const float* __restrict__ in, __nv_bfloat16* __restrict__ out, int n4)
{
    int i = blockIdx.x * blockDim.x + threadIdx.x;
    if (i < n4) {
        float4 v = reinterpret_cast<const float4*>(in)[i];
        __nv_bfloat162 a = __floats2bfloat162_rn(v.x, v.y);
        __nv_bfloat162 b = __floats2bfloat162_rn(v.z, v.w);
        uint2 u;
        u.x = *reinterpret_cast<unsigned*>(&a);
        u.y = *reinterpret_cast<unsigned*>(&b);
        reinterpret_cast<uint2*>(out)[i] = u;
    }
}

// ---------------- cp.async helper ---------------------------------------------
__device__ __forceinline__ void cp16(void* dst, const void* src) {
    unsigned d = (unsigned)__cvta_generic_to_shared(dst);
    asm volatile("cp.async.cg.shared.global [%0], [%1], 16;\n" :: "r"(d), "l"(src));
}

// ---------------- bf16 WMMA GEMM -----------------------------------------------
// BM=256, BN=128, BK=32; 8 warps, warp tile 64x64. 3-stage cp.async ring.
// OUT16=0: write fp32 to Cf.  OUT16=1: write bf16 to C16 (via smem staging).
template <int RELU, int OUT16>
__global__ __launch_bounds__(256) void bf16_gemm_bias(
    const __nv_bfloat16* __restrict__ A, const __nv_bfloat16* __restrict__ W,
    const float* __restrict__ bias, float* __restrict__ Cf,
    __nv_bfloat16* __restrict__ C16, int M, int N, int K)
{
    constexpr int BM = 256, BN = 128, BK = 32;
    constexpr int LDA = 40;
    constexpr int LDB = 136;
    constexpr int ASTG = BM * LDA;
    constexpr int BSTG = BK * LDB;
    extern __shared__ __nv_bfloat16 gs[];
    __nv_bfloat16* const Asm = gs;
    __nv_bfloat16* const Bsm = gs + 3 * ASTG;

    const int tid = threadIdx.x;
    const int wid = tid >> 5;
    const int wm  = wid >> 1;
    const int wn  = wid & 1;
    const int bm  = blockIdx.y * BM;
    const int bn  = blockIdx.x * BN;

    wmma::fragment<wmma::accumulator, 16, 16, 16, float> acc[4][4];

    {
        float* fs = reinterpret_cast<float*>(gs);
        int rr = tid >> 5;
        int n4 = (tid & 31) << 2;
        float4 bv = *reinterpret_cast<const float4*>(bias + bn + n4);
        *reinterpret_cast<float4*>(&fs[rr * 136 + n4])       = bv;
        *reinterpret_cast<float4*>(&fs[(rr + 8) * 136 + n4]) = bv;
        __syncthreads();
        #pragma unroll
        for (int fc = 0; fc < 4; fc++) {
            wmma::load_matrix_sync(acc[0][fc], &fs[wn * 64 + fc * 16], 136,
                                   wmma::mem_row_major);
            #pragma unroll
            for (int fr = 1; fr < 4; fr++)
                #pragma unroll
                for (int e = 0; e < acc[0][fc].num_elements; e++)
                    acc[fr][fc].x[e] = acc[0][fc].x[e];
        }
        __syncthreads();
    }

    const int arow  = tid >> 2;
    const int apart = (tid & 3) * 8;
    const int brow  = tid >> 4;
    const int bpart = (tid & 15) * 8;
    const __nv_bfloat16* const Ab = A + (size_t)bm * K;
    const __nv_bfloat16* const Wb = W + bn;

#define GISS(st, k0)                                                             \
    do {                                                                         \
        __nv_bfloat16* as = Asm + (st) * ASTG;                                   \
        __nv_bfloat16* bs = Bsm + (st) * BSTG;                                   \
        cp16(&as[(arow      ) * LDA + apart], Ab + (size_t)(arow      ) * K + (k0) + apart); \
        cp16(&as[(arow +  64) * LDA + apart], Ab + (size_t)(arow +  64) * K + (k0) + apart); \
        cp16(&as[(arow + 128) * LDA + apart], Ab + (size_t)(arow + 128) * K + (k0) + apart); \
        cp16(&as[(arow + 192) * LDA + apart], Ab + (size_t)(arow + 192) * K + (k0) + apart); \
        cp16(&bs[(brow     ) * LDB + bpart], Wb + (size_t)((k0) + brow     ) * N + bpart);   \
        cp16(&bs[(brow + 16) * LDB + bpart], Wb + (size_t)((k0) + brow + 16) * N + bpart);   \
        asm volatile("cp.async.commit_group;\n");                                \
    } while (0)

    const int NS = K / BK;
    GISS(0, 0);
    if (NS > 1) GISS(1, BK);

    int st = 0;
    for (int s = 0; s < NS; s++) {
        asm volatile("cp.async.wait_group 1;\n");
        __syncthreads();

        const __nv_bfloat16* as = Asm + st * ASTG;
        const __nv_bfloat16* bs = Bsm + st * BSTG;
        #pragma unroll
        for (int kk = 0; kk < BK; kk += 16) {
            wmma::fragment<wmma::matrix_a, 16, 16, 16, __nv_bfloat16,
                           wmma::row_major> af[4];
            wmma::fragment<wmma::matrix_b, 16, 16, 16, __nv_bfloat16,
                           wmma::row_major> bf[4];
            #pragma unroll
            for (int fr = 0; fr < 4; fr++)
                wmma::load_matrix_sync(af[fr], &as[(wm * 64 + fr * 16) * LDA + kk], LDA);
            #pragma unroll
            for (int fc = 0; fc < 4; fc++)
                wmma::load_matrix_sync(bf[fc], &bs[kk * LDB + wn * 64 + fc * 16], LDB);
            #pragma unroll
            for (int fr = 0; fr < 4; fr++)
                #pragma unroll
                for (int fc = 0; fc < 4; fc++)
                    wmma::mma_sync(acc[fr][fc], af[fr], bf[fc], acc[fr][fc]);
        }

        if (s + 2 < NS) {
            int nst = (st + 2) % 3;
            GISS(nst, (s + 2) * BK);
        }
        st = (st + 1) % 3;
    }
#undef GISS

    if (OUT16) {
        __syncthreads();   // mainloop smem free; reuse for staging
        float* stg = reinterpret_cast<float*>(gs) + wid * 256;
        const int lane = tid & 31;
        const int row  = lane >> 1;
        const int col  = (lane & 1) * 8;
        #pragma unroll
        for (int fr = 0; fr < 4; fr++)
            #pragma unroll
            for (int fc = 0; fc < 4; fc++) {
                if (RELU) {
                    #pragma unroll
                    for (int e = 0; e < acc[fr][fc].num_elements; e++)
                        acc[fr][fc].x[e] = fmaxf(acc[fr][fc].x[e], 0.0f);
                }
                wmma::store_matrix_sync(stg, acc[fr][fc], 16, wmma::mem_row_major);
                __syncwarp();
                float4 a  = *reinterpret_cast<float4*>(&stg[row * 16 + col]);
                float4 b4 = *reinterpret_cast<float4*>(&stg[row * 16 + col + 4]);
                __nv_bfloat162 p0 = __floats2bfloat162_rn(a.x,  a.y);
                __nv_bfloat162 p1 = __floats2bfloat162_rn(a.z,  a.w);
                __nv_bfloat162 p2 = __floats2bfloat162_rn(b4.x, b4.y);
                __nv_bfloat162 p3 = __floats2bfloat162_rn(b4.z, b4.w);
                uint4 u;
                u.x = *reinterpret_cast<unsigned*>(&p0);
                u.y = *reinterpret_cast<unsigned*>(&p1);
                u.z = *reinterpret_cast<unsigned*>(&p2);
                u.w = *reinterpret_cast<unsigned*>(&p3);
                *reinterpret_cast<uint4*>(
                    C16 + (size_t)(bm + wm * 64 + fr * 16 + row) * N
                        + bn + wn * 64 + fc * 16 + col) = u;
                __syncwarp();
            }
    } else {
        #pragma unroll
        for (int fr = 0; fr < 4; fr++)
            #pragma unroll
            for (int fc = 0; fc < 4; fc++) {
                if (RELU) {
                    #pragma unroll
                    for (int e = 0; e < acc[fr][fc].num_elements; e++)
                        acc[fr][fc].x[e] = fmaxf(acc[fr][fc].x[e], 0.0f);
                }
                float* cp = Cf + (size_t)(bm + wm * 64 + fr * 16) * N
                               + bn + wn * 64 + fc * 16;
                wmma::store_matrix_sync(cp, acc[fr][fc], N, wmma::mem_row_major);
            }
    }
}

#define GSMEM_BYTES ((3 * (256 * 40) + 3 * (32 * 136)) * 2)   // 87552

// ============== tensor-core flash attention (tf32 mma.sync, dk=64) ============
// cp.async double-buffered K/V (raw fp32 bits consumed as tf32). Output bf16.
#define FLDK 68
#define FLDV 72
#define FLDP 68
#define FSTG (64 * FLDK + 64 * FLDV)            // 8960 floats per stage
#define FPS_OFF (2 * FSTG)                       // 17920
#define FSMEM_FLOATS (FPS_OFF + 128 * FLDP)      // 26624
#define FSMEM_BYTES  (FSMEM_FLOATS * 4)          // 106496

__device__ __forceinline__ unsigned f2tf(float x) {
    unsigned u;
    asm("cvt.rna.tf32.f32 %0, %1;" : "=r"(u) : "f"(x));
    return u;
}

__device__ __forceinline__ void mma_tf32(float* d, const unsigned* a,
                                         const unsigned* b) {
    asm volatile(
        "mma.sync.aligned.m16n8k8.row.col.f32.tf32.tf32.f32 "
        "{%0,%1,%2,%3}, {%4,%5,%6,%7}, {%8,%9}, {%0,%1,%2,%3};\n"
        : "+f"(d[0]), "+f"(d[1]), "+f"(d[2]), "+f"(d[3])
        : "r"(a[0]), "r"(a[1]), "r"(a[2]), "r"(a[3]), "r"(b[0]), "r"(b[1]));
}

__global__ __launch_bounds__(256) void flash_attn_tc(
    const float* __restrict__ Qg, const float* __restrict__ Kg,
    const float* __restrict__ Vg, __nv_bfloat16* __restrict__ Og16,
    int Sq, int Skv)
{
    extern __shared__ float fsm[];
    unsigned* smu = reinterpret_cast<unsigned*>(fsm);

    const int tid  = threadIdx.x;
    const int lane = tid & 31;
    const int w    = tid >> 5;
    const int q0   = blockIdx.x * 128;
    const int h    = blockIdx.y;
    const int b    = blockIdx.z;
    const int r0   = lane >> 2;
    const int cq   = lane & 3;
    const float scale = 0.125f;

#define FISS(st, kvoff)                                                          \
    do {                                                                         \
        float* kb = fsm + (st) * FSTG;                                           \
        float* vb = kb + 64 * FLDK;                                              \
        _Pragma("unroll")                                                        \
        for (int i = 0; i < 4; i++) {                                            \
            int c = tid + 256 * i;                                               \
            int r = c >> 4;                                                      \
            int c16 = (c & 15) << 2;                                             \
            size_t gb = (size_t)(b * Skv + (kvoff) + r) * DMODEL + h * DKH + c16;\
            cp16(&kb[r * FLDK + c16], Kg + gb);                                  \
            cp16(&vb[r * FLDV + c16], Vg + gb);                                  \
        }                                                                        \
        asm volatile("cp.async.commit_group;\n");                                \
    } while (0)

    FISS(0, 0);

    // ---- Q fragments in registers (scaled + tf32) ----
    unsigned qa[8][4];
    {
        const float* Qb = Qg + (size_t)(b * Sq + q0 + w * 16) * DMODEL + h * DKH;
        #pragma unroll
        for (int ds = 0; ds < 8; ds++) {
            int c = ds * 8 + cq;
            qa[ds][0] = f2tf(scale * Qb[(size_t)r0       * DMODEL + c]);
            qa[ds][1] = f2tf(scale * Qb[(size_t)(r0 + 8) * DMODEL + c]);
            qa[ds][2] = f2tf(scale * Qb[(size_t)r0       * DMODEL + c + 4]);
            qa[ds][3] = f2tf(scale * Qb[(size_t)(r0 + 8) * DMODEL + c + 4]);
        }
    }

    float m0 = -1e30f, m1 = -1e30f, l0 = 0.0f, l1 = 0.0f;
    float o[8][4];
    #pragma unroll
    for (int nt = 0; nt < 8; nt++)
        o[nt][0] = o[nt][1] = o[nt][2] = o[nt][3] = 0.0f;

    unsigned* const pbase = smu + FPS_OFF + (w * 16) * FLDP;
    const int NS = Skv / 64;

    for (int s = 0; s < NS; s++) {
        if (s + 1 < NS) {
            __syncthreads();           // all warps done with the buffer being refilled
            FISS((s + 1) & 1, (s + 1) * 64);
            asm volatile("cp.async.wait_group 1;\n");
        } else {
            asm volatile("cp.async.wait_group 0;\n");
        }
        __syncthreads();               // stage s visible to all threads

        const unsigned* kbase = smu + (s & 1) * FSTG;
        const unsigned* vbase = kbase + 64 * FLDK;

        // ---- S = (Q*scale) K^T ----
        float sc[8][4];
        #pragma unroll
        for (int nt = 0; nt < 8; nt++)
            sc[nt][0] = sc[nt][1] = sc[nt][2] = sc[nt][3] = 0.0f;

        #pragma unroll
        for (int ds = 0; ds < 8; ds++) {
            #pragma unroll
            for (int nt = 0; nt < 8; nt++) {
                const unsigned* kp = kbase + (nt * 8 + r0) * FLDK + ds * 8 + cq;
                unsigned bb[2] = { kp[0], kp[4] };
                mma_tf32(sc[nt], qa[ds], bb);
            }
        }

        // ---- online softmax ----
        float mx0 = sc[0][0], mx1 = sc[0][2];
        #pragma unroll
        for (int nt = 0; nt < 8; nt++) {
            mx0 = fmaxf(mx0, fmaxf(sc[nt][0], sc[nt][1]));
            mx1 = fmaxf(mx1, fmaxf(sc[nt][2], sc[nt][3]));
        }
        mx0 = fmaxf(mx0, __shfl_xor_sync(0xffffffffu, mx0, 1));
        mx0 = fmaxf(mx0, __shfl_xor_sync(0xffffffffu, mx0, 2));
        mx1 = fmaxf(mx1, __shfl_xor_sync(0xffffffffu, mx1, 1));
        mx1 = fmaxf(mx1, __shfl_xor_sync(0xffffffffu, mx1, 2));

        float mn0 = fmaxf(m0, mx0), mn1 = fmaxf(m1, mx1);
        float al0 = __expf(m0 - mn0), al1 = __expf(m1 - mn1);
        m0 = mn0; m1 = mn1;

        float sum0 = 0.0f, sum1 = 0.0f;
        #pragma unroll
        for (int nt = 0; nt < 8; nt++) {
            sc[nt][0] = __expf(sc[nt][0] - mn0);
            sc[nt][1] = __expf(sc[nt][1] - mn0);
            sc[nt][2] = __expf(sc[nt][2] - mn1);
            sc[nt][3] = __expf(sc[nt][3] - mn1);
            sum0 += sc[nt][0] + sc[nt][1];
            sum1 += sc[nt][2] + sc[nt][3];
        }
        sum0 += __shfl_xor_sync(0xffffffffu, sum0, 1);
        sum0 += __shfl_xor_sync(0xffffffffu, sum0, 2);
        sum1 += __shfl_xor_sync(0xffffffffu, sum1, 1);
        sum1 += __shfl_xor_sync(0xffffffffu, sum1, 2);
        l0 = l0 * al0 + sum0;
        l1 = l1 * al1 + sum1;

        // ---- rescale O, write P (raw fp32 bits) to warp-private strip ----
        #pragma unroll
        for (int nt = 0; nt < 8; nt++) {
            o[nt][0] *= al0; o[nt][1] *= al0;
            o[nt][2] *= al1; o[nt][3] *= al1;
            uint2 p01 = make_uint2(__float_as_uint(sc[nt][0]), __float_as_uint(sc[nt][1]));
            uint2 p23 = make_uint2(__float_as_uint(sc[nt][2]), __float_as_uint(sc[nt][3]));
            *reinterpret_cast<uint2*>(pbase + r0 * FLDP + nt * 8 + 2 * cq)       = p01;
            *reinterpret_cast<uint2*>(pbase + (r0 + 8) * FLDP + nt * 8 + 2 * cq) = p23;
        }
        __syncwarp();

        // ---- O += P @ V ----
        #pragma unroll
        for (int kk = 0; kk < 8; kk++) {
            const unsigned* pp = pbase + r0 * FLDP + kk * 8 + cq;
            unsigned pa[4];
            pa[0] = pp[0];
            pa[1] = pp[8 * FLDP];
            pa[2] = pp[4];
            pa[3] = pp[8 * FLDP + 4];
            #pragma unroll
            for (int nt = 0; nt < 8; nt++) {
                const unsigned* vp = vbase + (kk * 8 + cq) * FLDV + nt * 8 + r0;
                unsigned bb[2] = { vp[0], vp[4 * FLDV] };
                mma_tf32(o[nt], pa, bb);
            }
        }
    }
#undef FISS

    // ---- epilogue: O / l, write bf16 ----
    const float i0 = 1.0f / l0, i1 = 1.0f / l1;
    __nv_bfloat16* Ob = Og16 + (size_t)(b * Sq + q0 + w * 16) * DMODEL + h * DKH;
    #pragma unroll
    for (int nt = 0; nt < 8; nt++) {
        __nv_bfloat162 v0 = __floats2bfloat162_rn(o[nt][0] * i0, o[nt][1] * i0);
        __nv_bfloat162 v1 = __floats2bfloat162_rn(o[nt][2] * i1, o[nt][3] * i1);
        *reinterpret_cast<unsigned*>(Ob + (size_t)r0 * DMODEL + nt * 8 + 2 * cq) =
            *reinterpret_cast<unsigned*>(&v0);
        *reinterpret_cast<unsigned*>(Ob + (size_t)(r0 + 8) * DMODEL + nt * 8 + 2 * cq) =
            *reinterpret_cast<unsigned*>(&v1);
    }
}

// ---------------- out = LayerNorm(a + c) * g + b  (+ optional bf16 copy) ------
__global__ __launch_bounds__(256) void add_ln_kernel(
    const float* __restrict__ a, const float* __restrict__ cadd,
    const float* __restrict__ g, const float* __restrict__ be,
    float* __restrict__ out, __nv_bfloat16* __restrict__ out16)
{
    __shared__ float red[16];
    const int row = blockIdx.x;
    const int tid = threadIdx.x;
    const size_t base = (size_t)row * DMODEL + tid * 4;

    float4 av = *reinterpret_cast<const float4*>(a + base);
    float4 cv = *reinterpret_cast<const float4*>(cadd + base);
    float x0 = av.x + cv.x, x1 = av.y + cv.y;
    float x2 = av.z + cv.z, x3 = av.w + cv.w;

    float s  = x0 + x1 + x2 + x3;
    float ss = x0 * x0 + x1 * x1 + x2 * x2 + x3 * x3;
    #pragma unroll
    for (int off = 16; off; off >>= 1) {
        s  += __shfl_xor_sync(0xffffffffu, s,  off);
        ss += __shfl_xor_sync(0xffffffffu, ss, off);
    }
    if ((tid & 31) == 0) { red[tid >> 5] = s; red[8 + (tid >> 5)] = ss; }
    __syncthreads();
    float ts = 0.0f, tss = 0.0f;
    #pragma unroll
    for (int i = 0; i < 8; i++) { ts += red[i]; tss += red[8 + i]; }

    const float mu  = ts * (1.0f / DMODEL);
    const float var = tss * (1.0f / DMODEL) - mu * mu;
    const float inv = rsqrtf(var + 1e-5f);

    float4 gv = *reinterpret_cast<const float4*>(g  + tid * 4);
    float4 bv = *reinterpret_cast<const float4*>(be + tid * 4);
    float4 ov;
    ov.x = (x0 - mu) * inv * gv.x + bv.x;
    ov.y = (x1 - mu) * inv * gv.y + bv.y;
    ov.z = (x2 - mu) * inv * gv.z + bv.z;
    ov.w = (x3 - mu) * inv * gv.w + bv.w;
    *reinterpret_cast<float4*>(out + base) = ov;

    if (out16) {
        __nv_bfloat162 p0 = __floats2bfloat162_rn(ov.x, ov.y);
        __nv_bfloat162 p1 = __floats2bfloat162_rn(ov.z, ov.w);
        uint2 u;
        u.x = *reinterpret_cast<unsigned*>(&p0);
        u.y = *reinterpret_cast<unsigned*>(&p1);
        *reinterpret_cast<uint2*>(out16 + base) = u;
    }
}

// ------------------------------- host driver ----------------------------------
static inline void conv_f2bf(const float* in, __nv_bfloat16* out, int n) {
    int n4 = n >> 2;
    f2bf_kernel<<<(n4 + 255) / 256, 256>>>(in, out, n4);
}

static inline void launch_gemm16(const __nv_bfloat16* A, const __nv_bfloat16* W,
                                 const float* B, float* Cf, int M, int N, int K)
{
    dim3 grid(N / 128, M / 256), blk(256);
    bf16_gemm_bias<0, 0><<<grid, blk, GSMEM_BYTES>>>(A, W, B, Cf, nullptr, M, N, K);
}

static inline void launch_gemm16_relu_bf16out(
    const __nv_bfloat16* A, const __nv_bfloat16* W,
    const float* B, __nv_bfloat16* C16, int M, int N, int K)
{
    dim3 grid(N / 128, M / 256), blk(256);
    bf16_gemm_bias<1, 1><<<grid, blk, GSMEM_BYTES>>>(A, W, B, nullptr, C16, M, N, K);
}

extern "C" void kernel_launch(void* const* d_in, const int* in_sizes, int n_in,
                              void* d_out, int out_size)
{
    const float* src   = (const float*)d_in[0];
    const float* tgt   = (const float*)d_in[1];
    const float* sa_wq = (const float*)d_in[2];
    const float* sa_bq = (const float*)d_in[3];
    const float* sa_wk = (const float*)d_in[4];
    const float* sa_bk = (const float*)d_in[5];
    const float* sa_wv = (const float*)d_in[6];
    const float* sa_bv = (const float*)d_in[7];
    const float* sa_wo = (const float*)d_in[8];
    const float* sa_bo = (const float*)d_in[9];
    const float* ca_wq = (const float*)d_in[10];
    const float* ca_bq = (const float*)d_in[11];
    const float* ca_wk = (const float*)d_in[12];
    const float* ca_bk = (const float*)d_in[13];
    const float* ca_wv = (const float*)d_in[14];
    const float* ca_bv = (const float*)d_in[15];
    const float* ca_wo = (const float*)d_in[16];
    const float* ca_bo = (const float*)d_in[17];
    const float* ff_w1 = (const float*)d_in[18];
    const float* ff_b1 = (const float*)d_in[19];
    const float* ff_w2 = (const float*)d_in[20];
    const float* ff_b2 = (const float*)d_in[21];
    const float* ln1_g = (const float*)d_in[22];
    const float* ln1_b = (const float*)d_in[23];
    const float* ln2_g = (const float*)d_in[24];
    const float* ln2_b = (const float*)d_in[25];
    const float* ln3_g = (const float*)d_in[26];
    const float* ln3_b = (const float*)d_in[27];
    float* out = (float*)d_out;

    float *q, *k, *v, *x1, *x2, *t;
    __nv_bfloat16 *a16, *h16, *w16;
    cudaGetSymbolAddress((void**)&q,   g_q);
    cudaGetSymbolAddress((void**)&k,   g_k);
    cudaGetSymbolAddress((void**)&v,   g_v);
    cudaGetSymbolAddress((void**)&x1,  g_x1);
    cudaGetSymbolAddress((void**)&x2,  g_x2);
    cudaGetSymbolAddress((void**)&t,   g_t);
    cudaGetSymbolAddress((void**)&a16, g_a16);
    cudaGetSymbolAddress((void**)&h16, g_h16);
    cudaGetSymbolAddress((void**)&w16, g_w16);

    const int NMM = MTOK * DMODEL;
    const int NW  = DMODEL * DMODEL;
    __nv_bfloat16* A0 = a16;
    __nv_bfloat16* A1 = a16 + NMM;

    cudaFuncSetAttribute(flash_attn_tc,
                         cudaFuncAttributeMaxDynamicSharedMemorySize, FSMEM_BYTES);
    cudaFuncSetAttribute(bf16_gemm_bias<0, 0>,
                         cudaFuncAttributeMaxDynamicSharedMemorySize, GSMEM_BYTES);
    cudaFuncSetAttribute(bf16_gemm_bias<1, 1>,
                         cudaFuncAttributeMaxDynamicSharedMemorySize, GSMEM_BYTES);

    dim3 fgrid(SEQ / 128, NHEAD, BATCH), blk(256);

    // ---- self-attention block ----
    conv_f2bf(tgt, A0, NMM);
    conv_f2bf(sa_wq, w16, NW);
    launch_gemm16(A0, w16, sa_bq, q, MTOK, DMODEL, DMODEL);
    conv_f2bf(sa_wk, w16, NW);
    launch_gemm16(A0, w16, sa_bk, k, MTOK, DMODEL, DMODEL);
    conv_f2bf(sa_wv, w16, NW);
    launch_gemm16(A0, w16, sa_bv, v, MTOK, DMODEL, DMODEL);
    flash_attn_tc<<<fgrid, blk, FSMEM_BYTES>>>(q, k, v, A1, SEQ, SEQ);
    conv_f2bf(sa_wo, w16, NW);
    launch_gemm16(A1, w16, sa_bo, t, MTOK, DMODEL, DMODEL);
    add_ln_kernel<<<MTOK, blk>>>(tgt, t, ln1_g, ln1_b, x1, A0);

    // ---- cross-attention block ----
    conv_f2bf(ca_wq, w16, NW);
    launch_gemm16(A0, w16, ca_bq, q, MTOK, DMODEL, DMODEL);
    conv_f2bf(src, A1, NMM);
    conv_f2bf(ca_wk, w16, NW);
    launch_gemm16(A1, w16, ca_bk, k, MTOK, DMODEL, DMODEL);
    conv_f2bf(ca_wv, w16, NW);
    launch_gemm16(A1, w16, ca_bv, v, MTOK, DMODEL, DMODEL);
    flash_attn_tc<<<fgrid, blk, FSMEM_BYTES>>>(q, k, v, A1, SEQ, SEQ);
    conv_f2bf(ca_wo, w16, NW);
    launch_gemm16(A1, w16, ca_bo, t, MTOK, DMODEL, DMODEL);
    add_ln_kernel<<<MTOK, blk>>>(x1, t, ln2_g, ln2_b, x2, A0);

    // ---- feed-forward block ----
    conv_f2bf(ff_w1, w16, DMODEL * DFF);
    launch_gemm16_relu_bf16out(A0, w16, ff_b1, h16, MTOK, DFF, DMODEL);
    conv_f2bf(ff_w2, w16, DFF * DMODEL);
    launch_gemm16(h16, w16, ff_b2, t, MTOK, DMODEL, DFF);
    add_ln_kernel<<<MTOK, blk>>>(x2, t, ln3_g, ln3_b, out, nullptr);
}

// round 12
// speedup vs baseline: 4.2992x; 1.1458x over previous
#include <cuda_runtime.h>
#include <cuda_bf16.h>
#include <mma.h>

using namespace nvcuda;

#define DMODEL 1024
#define NHEAD  16
#define DKH    64
#define DFF    4096
#define BATCH  4
#define SEQ    2048
#define MTOK   (BATCH * SEQ)

// ---------------- scratch (device globals; no allocation allowed) -------------
__device__ float g_x1[MTOK * DMODEL];
__device__ float g_x2[MTOK * DMODEL];
__device__ float g_t[MTOK * DMODEL];
__device__ __nv_bfloat16 g_q16[MTOK * DMODEL];
__device__ __nv_bfloat16 g_k16[MTOK * DMODEL];
__device__ __nv_bfloat16 g_v16[MTOK * DMODEL];
__device__ __nv_bfloat16 g_a16[2 * MTOK * DMODEL];  // two activation slots
__device__ __nv_bfloat16 g_h16[MTOK * DFF];         // FF hidden (bf16)
__device__ __nv_bfloat16 g_w16[DMODEL * DFF];       // weight scratch

// ---------------- fp32 -> bf16 conversion (weights + src/tgt) -----------------
__global__ __launch_bounds__(256) void f2bf_kernel(
    const float* __restrict__ in, __nv_bfloat16* __restrict__ out, int n4)
{
    int i = blockIdx.x * blockDim.x + threadIdx.x;
    if (i < n4) {
        float4 v = reinterpret_cast<const float4*>(in)[i];
        __nv_bfloat162 a = __floats2bfloat162_rn(v.x, v.y);
        __nv_bfloat162 b = __floats2bfloat162_rn(v.z, v.w);
        uint2 u;
        u.x = *reinterpret_cast<unsigned*>(&a);
        u.y = *reinterpret_cast<unsigned*>(&b);
        reinterpret_cast<uint2*>(out)[i] = u;
    }
}

// ---------------- cp.async helper ---------------------------------------------
__device__ __forceinline__ void cp16(void* dst, const void* src) {
    unsigned d = (unsigned)__cvta_generic_to_shared(dst);
    asm volatile("cp.async.cg.shared.global [%0], [%1], 16;\n" :: "r"(d), "l"(src));
}

// ---------------- bf16 WMMA GEMM -----------------------------------------------
// BM=256, BN=128, BK=32; 8 warps, warp tile 64x64. 3-stage cp.async ring.
// OUT16=0: fp32 out to Cf.  OUT16=1: bf16 out to C16 (smem staging).
template <int RELU, int OUT16>
__global__ __launch_bounds__(256) void bf16_gemm_bias(
    const __nv_bfloat16* __restrict__ A, const __nv_bfloat16* __restrict__ W,
    const float* __restrict__ bias, float* __restrict__ Cf,
    __nv_bfloat16* __restrict__ C16, int M, int N, int K)
{
    constexpr int BM = 256, BN = 128, BK = 32;
    constexpr int LDA = 40;
    constexpr int LDB = 136;
    constexpr int ASTG = BM * LDA;
    constexpr int BSTG = BK * LDB;
    extern __shared__ __nv_bfloat16 gs[];
    __nv_bfloat16* const Asm = gs;
    __nv_bfloat16* const Bsm = gs + 3 * ASTG;

    const int tid = threadIdx.x;
    const int wid = tid >> 5;
    const int wm  = wid >> 1;
    const int wn  = wid & 1;
    const int bm  = blockIdx.y * BM;
    const int bn  = blockIdx.x * BN;

    wmma::fragment<wmma::accumulator, 16, 16, 16, float> acc[4][4];

    {
        float* fs = reinterpret_cast<float*>(gs);
        int rr = tid >> 5;
        int n4 = (tid & 31) << 2;
        float4 bv = *reinterpret_cast<const float4*>(bias + bn + n4);
        *reinterpret_cast<float4*>(&fs[rr * 136 + n4])       = bv;
        *reinterpret_cast<float4*>(&fs[(rr + 8) * 136 + n4]) = bv;
        __syncthreads();
        #pragma unroll
        for (int fc = 0; fc < 4; fc++) {
            wmma::load_matrix_sync(acc[0][fc], &fs[wn * 64 + fc * 16], 136,
                                   wmma::mem_row_major);
            #pragma unroll
            for (int fr = 1; fr < 4; fr++)
                #pragma unroll
                for (int e = 0; e < acc[0][fc].num_elements; e++)
                    acc[fr][fc].x[e] = acc[0][fc].x[e];
        }
        __syncthreads();
    }

    const int arow  = tid >> 2;
    const int apart = (tid & 3) * 8;
    const int brow  = tid >> 4;
    const int bpart = (tid & 15) * 8;
    const __nv_bfloat16* const Ab = A + (size_t)bm * K;
    const __nv_bfloat16* const Wb = W + bn;

#define GISS(st, k0)                                                             \
    do {                                                                         \
        __nv_bfloat16* as = Asm + (st) * ASTG;                                   \
        __nv_bfloat16* bs = Bsm + (st) * BSTG;                                   \
        cp16(&as[(arow      ) * LDA + apart], Ab + (size_t)(arow      ) * K + (k0) + apart); \
        cp16(&as[(arow +  64) * LDA + apart], Ab + (size_t)(arow +  64) * K + (k0) + apart); \
        cp16(&as[(arow + 128) * LDA + apart], Ab + (size_t)(arow + 128) * K + (k0) + apart); \
        cp16(&as[(arow + 192) * LDA + apart], Ab + (size_t)(arow + 192) * K + (k0) + apart); \
        cp16(&bs[(brow     ) * LDB + bpart], Wb + (size_t)((k0) + brow     ) * N + bpart);   \
        cp16(&bs[(brow + 16) * LDB + bpart], Wb + (size_t)((k0) + brow + 16) * N + bpart);   \
        asm volatile("cp.async.commit_group;\n");                                \
    } while (0)

    const int NS = K / BK;
    GISS(0, 0);
    if (NS > 1) GISS(1, BK);

    int st = 0;
    for (int s = 0; s < NS; s++) {
        asm volatile("cp.async.wait_group 1;\n");
        __syncthreads();

        const __nv_bfloat16* as = Asm + st * ASTG;
        const __nv_bfloat16* bs = Bsm + st * BSTG;
        #pragma unroll
        for (int kk = 0; kk < BK; kk += 16) {
            wmma::fragment<wmma::matrix_a, 16, 16, 16, __nv_bfloat16,
                           wmma::row_major> af[4];
            wmma::fragment<wmma::matrix_b, 16, 16, 16, __nv_bfloat16,
                           wmma::row_major> bf[4];
            #pragma unroll
            for (int fr = 0; fr < 4; fr++)
                wmma::load_matrix_sync(af[fr], &as[(wm * 64 + fr * 16) * LDA + kk], LDA);
            #pragma unroll
            for (int fc = 0; fc < 4; fc++)
                wmma::load_matrix_sync(bf[fc], &bs[kk * LDB + wn * 64 + fc * 16], LDB);
            #pragma unroll
            for (int fr = 0; fr < 4; fr++)
                #pragma unroll
                for (int fc = 0; fc < 4; fc++)
                    wmma::mma_sync(acc[fr][fc], af[fr], bf[fc], acc[fr][fc]);
        }

        if (s + 2 < NS) {
            int nst = (st + 2) % 3;
            GISS(nst, (s + 2) * BK);
        }
        st = (st + 1) % 3;
    }
#undef GISS

    if (OUT16) {
        __syncthreads();
        float* stg = reinterpret_cast<float*>(gs) + wid * 256;
        const int lane = tid & 31;
        const int row  = lane >> 1;
        const int col  = (lane & 1) * 8;
        #pragma unroll
        for (int fr = 0; fr < 4; fr++)
            #pragma unroll
            for (int fc = 0; fc < 4; fc++) {
                if (RELU) {
                    #pragma unroll
                    for (int e = 0; e < acc[fr][fc].num_elements; e++)
                        acc[fr][fc].x[e] = fmaxf(acc[fr][fc].x[e], 0.0f);
                }
                wmma::store_matrix_sync(stg, acc[fr][fc], 16, wmma::mem_row_major);
                __syncwarp();
                float4 a  = *reinterpret_cast<float4*>(&stg[row * 16 + col]);
                float4 b4 = *reinterpret_cast<float4*>(&stg[row * 16 + col + 4]);
                __nv_bfloat162 p0 = __floats2bfloat162_rn(a.x,  a.y);
                __nv_bfloat162 p1 = __floats2bfloat162_rn(a.z,  a.w);
                __nv_bfloat162 p2 = __floats2bfloat162_rn(b4.x, b4.y);
                __nv_bfloat162 p3 = __floats2bfloat162_rn(b4.z, b4.w);
                uint4 u;
                u.x = *reinterpret_cast<unsigned*>(&p0);
                u.y = *reinterpret_cast<unsigned*>(&p1);
                u.z = *reinterpret_cast<unsigned*>(&p2);
                u.w = *reinterpret_cast<unsigned*>(&p3);
                *reinterpret_cast<uint4*>(
                    C16 + (size_t)(bm + wm * 64 + fr * 16 + row) * N
                        + bn + wn * 64 + fc * 16 + col) = u;
                __syncwarp();
            }
    } else {
        #pragma unroll
        for (int fr = 0; fr < 4; fr++)
            #pragma unroll
            for (int fc = 0; fc < 4; fc++) {
                if (RELU) {
                    #pragma unroll
                    for (int e = 0; e < acc[fr][fc].num_elements; e++)
                        acc[fr][fc].x[e] = fmaxf(acc[fr][fc].x[e], 0.0f);
                }
                float* cp = Cf + (size_t)(bm + wm * 64 + fr * 16) * N
                               + bn + wn * 64 + fc * 16;
                wmma::store_matrix_sync(cp, acc[fr][fc], N, wmma::mem_row_major);
            }
    }
}

#define GSMEM_BYTES ((3 * (256 * 40) + 3 * (32 * 136)) * 2)   // 87552

// ============== bf16 tensor-core flash attention (m16n8k16, dk=64) ============
// Q/K/V bf16 in gmem. K staged row-major via cp.async (double buffer).
// V register-prefetched from gmem and stored TRANSPOSED (d-major) in smem.
// P stored bf16x2 (exact A-fragment pairs). All strides 72 bf16 (36 words):
// fragment word addr ≡ r*36 + c ≡ r*4+c (mod 32) -> conflict-free.
#define HLDK 72
#define HLDV 72
#define HLDP 72
#define HKSTG (64 * HLDK)                  // 4608 bf16 per K stage
#define HVT_OFF (2 * HKSTG)                // 9216
#define HVSTG (64 * HLDV)                  // 4608 bf16 per Vt stage
#define HPS_OFF (HVT_OFF + 2 * HVSTG)      // 18432
#define HSMEM_H (HPS_OFF + 128 * HLDP)     // 27648 bf16
#define HSMEM_BYTES (HSMEM_H * 2)          // 55296 B

__device__ __forceinline__ void mma_bf16(float* d, const unsigned* a,
                                         const unsigned* b) {
    asm volatile(
        "mma.sync.aligned.m16n8k16.row.col.f32.bf16.bf16.f32 "
        "{%0,%1,%2,%3}, {%4,%5,%6,%7}, {%8,%9}, {%0,%1,%2,%3};\n"
        : "+f"(d[0]), "+f"(d[1]), "+f"(d[2]), "+f"(d[3])
        : "r"(a[0]), "r"(a[1]), "r"(a[2]), "r"(a[3]), "r"(b[0]), "r"(b[1]));
}

__global__ __launch_bounds__(256) void flash_attn_bf16(
    const __nv_bfloat16* __restrict__ Qg, const __nv_bfloat16* __restrict__ Kg,
    const __nv_bfloat16* __restrict__ Vg, __nv_bfloat16* __restrict__ Og16,
    int Sq, int Skv)
{
    extern __shared__ __nv_bfloat16 hsm[];
    unsigned* smw = reinterpret_cast<unsigned*>(hsm);

    const int tid  = threadIdx.x;
    const int lane = tid & 31;
    const int w    = tid >> 5;
    const int q0   = blockIdx.x * 128;
    const int h    = blockIdx.y;
    const int b    = blockIdx.z;
    const int r0   = lane >> 2;
    const int cq   = lane & 3;

    // K loader: 512 x 16B chunks, 2 per thread
    const int kc0 = tid, kc1 = tid + 256;
#define KISS(st, kvoff)                                                          \
    do {                                                                         \
        __nv_bfloat16* kb = hsm + (st) * HKSTG;                                  \
        { int r = kc0 >> 3, o8 = (kc0 & 7) * 8;                                  \
          cp16(&kb[r * HLDK + o8],                                               \
               Kg + (size_t)(b * Skv + (kvoff) + r) * DMODEL + h * DKH + o8); }  \
        { int r = kc1 >> 3, o8 = (kc1 & 7) * 8;                                  \
          cp16(&kb[r * HLDK + o8],                                               \
               Kg + (size_t)(b * Skv + (kvoff) + r) * DMODEL + h * DKH + o8); }  \
        asm volatile("cp.async.commit_group;\n");                                \
    } while (0)

    // V prefetch: thread owns kv-row vc, d-cols vd..vd+15
    const int vc = tid & 63;
    const int vd = (tid >> 6) * 16;
    uint4 vr0, vr1;
#define VLOAD(kvoff)                                                             \
    do {                                                                         \
        const uint4* vp = reinterpret_cast<const uint4*>(                        \
            Vg + (size_t)(b * Skv + (kvoff) + vc) * DMODEL + h * DKH + vd);      \
        vr0 = vp[0]; vr1 = vp[1];                                                \
    } while (0)

    KISS(0, 0);
    VLOAD(0);

    // Q fragments (bf16, scale 1/8 folded in: exact exponent shift)
    unsigned qa[4][4];
    {
        const __nv_bfloat162 s2 = __float2bfloat162_rn(0.125f);
        const __nv_bfloat16* Qb = Qg + (size_t)(b * Sq + q0 + w * 16) * DMODEL + h * DKH;
        #pragma unroll
        for (int ds = 0; ds < 4; ds++) {
            #pragma unroll
            for (int p = 0; p < 4; p++) {
                int rr = (p & 1) ? r0 + 8 : r0;
                int cc = ds * 16 + 2 * cq + ((p & 2) ? 8 : 0);
                __nv_bfloat162 x = *reinterpret_cast<const __nv_bfloat162*>(
                    Qb + (size_t)rr * DMODEL + cc);
                x = __hmul2(x, s2);
                qa[ds][p] = *reinterpret_cast<unsigned*>(&x);
            }
        }
    }

    float m0 = -1e30f, m1 = -1e30f, l0 = 0.0f, l1 = 0.0f;
    float o[8][4];
    #pragma unroll
    for (int nt = 0; nt < 8; nt++)
        o[nt][0] = o[nt][1] = o[nt][2] = o[nt][3] = 0.0f;

    unsigned* const pw = smw + (HPS_OFF >> 1) + (w * 16) * (HLDP >> 1);
    const int NS = Skv / 64;

    for (int s = 0; s < NS; s++) {
        // store V(s) transposed into Vt[s&1] (16-bit consecutive: conflict-free)
        {
            __nv_bfloat16* vt = hsm + HVT_OFF + (s & 1) * HVSTG;
            __nv_bfloat16 tmp[16];
            *reinterpret_cast<uint4*>(tmp)     = vr0;
            *reinterpret_cast<uint4*>(tmp + 8) = vr1;
            #pragma unroll
            for (int j = 0; j < 16; j++)
                vt[(vd + j) * HLDV + vc] = tmp[j];
        }
        if (s + 1 < NS) {
            __syncthreads();            // K buf (s+1)&1 free; Vt[s&1] stores done
            KISS((s + 1) & 1, (s + 1) * 64);
            VLOAD((s + 1) * 64);
            asm volatile("cp.async.wait_group 1;\n");
        } else {
            asm volatile("cp.async.wait_group 0;\n");
        }
        __syncthreads();                // K(s), Vt[s&1] visible

        const unsigned* kw  = smw + (((s & 1) * HKSTG) >> 1);
        const unsigned* vtw = smw + ((HVT_OFF + (s & 1) * HVSTG) >> 1);

        // ---- S = (Q/8) K^T : 4 k16-steps x 8 n-tiles ----
        float sc[8][4];
        #pragma unroll
        for (int nt = 0; nt < 8; nt++)
            sc[nt][0] = sc[nt][1] = sc[nt][2] = sc[nt][3] = 0.0f;

        #pragma unroll
        for (int ds = 0; ds < 4; ds++) {
            #pragma unroll
            for (int nt = 0; nt < 8; nt++) {
                const unsigned* kp = kw + (nt * 8 + r0) * 36 + ds * 8 + cq;
                unsigned bb[2] = { kp[0], kp[4] };
                mma_bf16(sc[nt], qa[ds], bb);
            }
        }

        // ---- online softmax ----
        float mx0 = sc[0][0], mx1 = sc[0][2];
        #pragma unroll
        for (int nt = 0; nt < 8; nt++) {
            mx0 = fmaxf(mx0, fmaxf(sc[nt][0], sc[nt][1]));
            mx1 = fmaxf(mx1, fmaxf(sc[nt][2], sc[nt][3]));
        }
        mx0 = fmaxf(mx0, __shfl_xor_sync(0xffffffffu, mx0, 1));
        mx0 = fmaxf(mx0, __shfl_xor_sync(0xffffffffu, mx0, 2));
        mx1 = fmaxf(mx1, __shfl_xor_sync(0xffffffffu, mx1, 1));
        mx1 = fmaxf(mx1, __shfl_xor_sync(0xffffffffu, mx1, 2));

        float mn0 = fmaxf(m0, mx0), mn1 = fmaxf(m1, mx1);
        float al0 = __expf(m0 - mn0), al1 = __expf(m1 - mn1);
        m0 = mn0; m1 = mn1;

        float sum0 = 0.0f, sum1 = 0.0f;
        #pragma unroll
        for (int nt = 0; nt < 8; nt++) {
            sc[nt][0] = __expf(sc[nt][0] - mn0);
            sc[nt][1] = __expf(sc[nt][1] - mn0);
            sc[nt][2] = __expf(sc[nt][2] - mn1);
            sc[nt][3] = __expf(sc[nt][3] - mn1);
            sum0 += sc[nt][0] + sc[nt][1];
            sum1 += sc[nt][2] + sc[nt][3];
        }
        sum0 += __shfl_xor_sync(0xffffffffu, sum0, 1);
        sum0 += __shfl_xor_sync(0xffffffffu, sum0, 2);
        sum1 += __shfl_xor_sync(0xffffffffu, sum1, 1);
        sum1 += __shfl_xor_sync(0xffffffffu, sum1, 2);
        l0 = l0 * al0 + sum0;
        l1 = l1 * al1 + sum1;

        // ---- rescale O; write P as bf16x2 to warp-private strip ----
        #pragma unroll
        for (int nt = 0; nt < 8; nt++) {
            o[nt][0] *= al0; o[nt][1] *= al0;
            o[nt][2] *= al1; o[nt][3] *= al1;
            __nv_bfloat162 p01 = __floats2bfloat162_rn(sc[nt][0], sc[nt][1]);
            __nv_bfloat162 p23 = __floats2bfloat162_rn(sc[nt][2], sc[nt][3]);
            pw[r0 * 36 + nt * 4 + cq]       = *reinterpret_cast<unsigned*>(&p01);
            pw[(r0 + 8) * 36 + nt * 4 + cq] = *reinterpret_cast<unsigned*>(&p23);
        }
        __syncwarp();

        // ---- O += P @ V : 4 k16-steps x 8 n-tiles ----
        #pragma unroll
        for (int kk = 0; kk < 4; kk++) {
            unsigned pa[4];
            pa[0] = pw[r0 * 36 + kk * 8 + cq];
            pa[1] = pw[(r0 + 8) * 36 + kk * 8 + cq];
            pa[2] = pw[r0 * 36 + kk * 8 + cq + 4];
            pa[3] = pw[(r0 + 8) * 36 + kk * 8 + cq + 4];
            #pragma unroll
            for (int nt = 0; nt < 8; nt++) {
                const unsigned* vp = vtw + (nt * 8 + r0) * 36 + kk * 8 + cq;
                unsigned bb[2] = { vp[0], vp[4] };
                mma_bf16(o[nt], pa, bb);
            }
        }
    }
#undef KISS
#undef VLOAD

    // ---- epilogue: O / l, write bf16 ----
    const float i0 = 1.0f / l0, i1 = 1.0f / l1;
    __nv_bfloat16* Ob = Og16 + (size_t)(b * Sq + q0 + w * 16) * DMODEL + h * DKH;
    #pragma unroll
    for (int nt = 0; nt < 8; nt++) {
        __nv_bfloat162 v0 = __floats2bfloat162_rn(o[nt][0] * i0, o[nt][1] * i0);
        __nv_bfloat162 v1 = __floats2bfloat162_rn(o[nt][2] * i1, o[nt][3] * i1);
        *reinterpret_cast<unsigned*>(Ob + (size_t)r0 * DMODEL + nt * 8 + 2 * cq) =
            *reinterpret_cast<unsigned*>(&v0);
        *reinterpret_cast<unsigned*>(Ob + (size_t)(r0 + 8) * DMODEL + nt * 8 + 2 * cq) =
            *reinterpret_cast<unsigned*>(&v1);
    }
}

// ---------------- out = LayerNorm(a + c) * g + b  (+ optional bf16 copy) ------
__global__ __launch_bounds__(256) void add_ln_kernel(
    const float* __restrict__ a, const float* __restrict__ cadd,
    const float* __restrict__ g, const float* __restrict__ be,
    float* __restrict__ out, __nv_bfloat16* __restrict__ out16)
{
    __shared__ float red[16];
    const int row = blockIdx.x;
    const int tid = threadIdx.x;
    const size_t base = (size_t)row * DMODEL + tid * 4;

    float4 av = *reinterpret_cast<const float4*>(a + base);
    float4 cv = *reinterpret_cast<const float4*>(cadd + base);
    float x0 = av.x + cv.x, x1 = av.y + cv.y;
    float x2 = av.z + cv.z, x3 = av.w + cv.w;

    float s  = x0 + x1 + x2 + x3;
    float ss = x0 * x0 + x1 * x1 + x2 * x2 + x3 * x3;
    #pragma unroll
    for (int off = 16; off; off >>= 1) {
        s  += __shfl_xor_sync(0xffffffffu, s,  off);
        ss += __shfl_xor_sync(0xffffffffu, ss, off);
    }
    if ((tid & 31) == 0) { red[tid >> 5] = s; red[8 + (tid >> 5)] = ss; }
    __syncthreads();
    float ts = 0.0f, tss = 0.0f;
    #pragma unroll
    for (int i = 0; i < 8; i++) { ts += red[i]; tss += red[8 + i]; }

    const float mu  = ts * (1.0f / DMODEL);
    const float var = tss * (1.0f / DMODEL) - mu * mu;
    const float inv = rsqrtf(var + 1e-5f);

    float4 gv = *reinterpret_cast<const float4*>(g  + tid * 4);
    float4 bv = *reinterpret_cast<const float4*>(be + tid * 4);
    float4 ov;
    ov.x = (x0 - mu) * inv * gv.x + bv.x;
    ov.y = (x1 - mu) * inv * gv.y + bv.y;
    ov.z = (x2 - mu) * inv * gv.z + bv.z;
    ov.w = (x3 - mu) * inv * gv.w + bv.w;
    *reinterpret_cast<float4*>(out + base) = ov;

    if (out16) {
        __nv_bfloat162 p0 = __floats2bfloat162_rn(ov.x, ov.y);
        __nv_bfloat162 p1 = __floats2bfloat162_rn(ov.z, ov.w);
        uint2 u;
        u.x = *reinterpret_cast<unsigned*>(&p0);
        u.y = *reinterpret_cast<unsigned*>(&p1);
        *reinterpret_cast<uint2*>(out16 + base) = u;
    }
}

// ------------------------------- host driver ----------------------------------
static inline void conv_f2bf(const float* in, __nv_bfloat16* out, int n) {
    int n4 = n >> 2;
    f2bf_kernel<<<(n4 + 255) / 256, 256>>>(in, out, n4);
}

static inline void launch_gemm16(const __nv_bfloat16* A, const __nv_bfloat16* W,
                                 const float* B, float* Cf, int M, int N, int K)
{
    dim3 grid(N / 128, M / 256), blk(256);
    bf16_gemm_bias<0, 0><<<grid, blk, GSMEM_BYTES>>>(A, W, B, Cf, nullptr, M, N, K);
}

static inline void launch_gemm16_bf16out(
    const __nv_bfloat16* A, const __nv_bfloat16* W,
    const float* B, __nv_bfloat16* C16, int M, int N, int K)
{
    dim3 grid(N / 128, M / 256), blk(256);
    bf16_gemm_bias<0, 1><<<grid, blk, GSMEM_BYTES>>>(A, W, B, nullptr, C16, M, N, K);
}

static inline void launch_gemm16_relu_bf16out(
    const __nv_bfloat16* A, const __nv_bfloat16* W,
    const float* B, __nv_bfloat16* C16, int M, int N, int K)
{
    dim3 grid(N / 128, M / 256), blk(256);
    bf16_gemm_bias<1, 1><<<grid, blk, GSMEM_BYTES>>>(A, W, B, nullptr, C16, M, N, K);
}

extern "C" void kernel_launch(void* const* d_in, const int* in_sizes, int n_in,
                              void* d_out, int out_size)
{
    const float* src   = (const float*)d_in[0];
    const float* tgt   = (const float*)d_in[1];
    const float* sa_wq = (const float*)d_in[2];
    const float* sa_bq = (const float*)d_in[3];
    const float* sa_wk = (const float*)d_in[4];
    const float* sa_bk = (const float*)d_in[5];
    const float* sa_wv = (const float*)d_in[6];
    const float* sa_bv = (const float*)d_in[7];
    const float* sa_wo = (const float*)d_in[8];
    const float* sa_bo = (const float*)d_in[9];
    const float* ca_wq = (const float*)d_in[10];
    const float* ca_bq = (const float*)d_in[11];
    const float* ca_wk = (const float*)d_in[12];
    const float* ca_bk = (const float*)d_in[13];
    const float* ca_wv = (const float*)d_in[14];
    const float* ca_bv = (const float*)d_in[15];
    const float* ca_wo = (const float*)d_in[16];
    const float* ca_bo = (const float*)d_in[17];
    const float* ff_w1 = (const float*)d_in[18];
    const float* ff_b1 = (const float*)d_in[19];
    const float* ff_w2 = (const float*)d_in[20];
    const float* ff_b2 = (const float*)d_in[21];
    const float* ln1_g = (const float*)d_in[22];
    const float* ln1_b = (const float*)d_in[23];
    const float* ln2_g = (const float*)d_in[24];
    const float* ln2_b = (const float*)d_in[25];
    const float* ln3_g = (const float*)d_in[26];
    const float* ln3_b = (const float*)d_in[27];
    float* out = (float*)d_out;

    float *x1, *x2, *t;
    __nv_bfloat16 *q16, *k16, *v16, *a16, *h16, *w16;
    cudaGetSymbolAddress((void**)&x1,  g_x1);
    cudaGetSymbolAddress((void**)&x2,  g_x2);
    cudaGetSymbolAddress((void**)&t,   g_t);
    cudaGetSymbolAddress((void**)&q16, g_q16);
    cudaGetSymbolAddress((void**)&k16, g_k16);
    cudaGetSymbolAddress((void**)&v16, g_v16);
    cudaGetSymbolAddress((void**)&a16, g_a16);
    cudaGetSymbolAddress((void**)&h16, g_h16);
    cudaGetSymbolAddress((void**)&w16, g_w16);

    const int NMM = MTOK * DMODEL;
    const int NW  = DMODEL * DMODEL;
    __nv_bfloat16* A0 = a16;
    __nv_bfloat16* A1 = a16 + NMM;

    cudaFuncSetAttribute(flash_attn_bf16,
                         cudaFuncAttributeMaxDynamicSharedMemorySize, HSMEM_BYTES);
    cudaFuncSetAttribute(bf16_gemm_bias<0, 0>,
                         cudaFuncAttributeMaxDynamicSharedMemorySize, GSMEM_BYTES);
    cudaFuncSetAttribute(bf16_gemm_bias<0, 1>,
                         cudaFuncAttributeMaxDynamicSharedMemorySize, GSMEM_BYTES);
    cudaFuncSetAttribute(bf16_gemm_bias<1, 1>,
                         cudaFuncAttributeMaxDynamicSharedMemorySize, GSMEM_BYTES);

    dim3 fgrid(SEQ / 128, NHEAD, BATCH), blk(256);

    // ---- self-attention block ----
    conv_f2bf(tgt, A0, NMM);
    conv_f2bf(sa_wq, w16, NW);
    launch_gemm16_bf16out(A0, w16, sa_bq, q16, MTOK, DMODEL, DMODEL);
    conv_f2bf(sa_wk, w16, NW);
    launch_gemm16_bf16out(A0, w16, sa_bk, k16, MTOK, DMODEL, DMODEL);
    conv_f2bf(sa_wv, w16, NW);
    launch_gemm16_bf16out(A0, w16, sa_bv, v16, MTOK, DMODEL, DMODEL);
    flash_attn_bf16<<<fgrid, blk, HSMEM_BYTES>>>(q16, k16, v16, A1, SEQ, SEQ);
    conv_f2bf(sa_wo, w16, NW);
    launch_gemm16(A1, w16, sa_bo, t, MTOK, DMODEL, DMODEL);
    add_ln_kernel<<<MTOK, blk>>>(tgt, t, ln1_g, ln1_b, x1, A0);

    // ---- cross-attention block ----
    conv_f2bf(ca_wq, w16, NW);
    launch_gemm16_bf16out(A0, w16, ca_bq, q16, MTOK, DMODEL, DMODEL);
    conv_f2bf(src, A1, NMM);
    conv_f2bf(ca_wk, w16, NW);
    launch_gemm16_bf16out(A1, w16, ca_bk, k16, MTOK, DMODEL, DMODEL);
    conv_f2bf(ca_wv, w16, NW);
    launch_gemm16_bf16out(A1, w16, ca_bv, v16, MTOK, DMODEL, DMODEL);
    flash_attn_bf16<<<fgrid, blk, HSMEM_BYTES>>>(q16, k16, v16, A1, SEQ, SEQ);
    conv_f2bf(ca_wo, w16, NW);
    launch_gemm16(A1, w16, ca_bo, t, MTOK, DMODEL, DMODEL);
    add_ln_kernel<<<MTOK, blk>>>(x1, t, ln2_g, ln2_b, x2, A0);

    // ---- feed-forward block ----
    conv_f2bf(ff_w1, w16, DMODEL * DFF);
    launch_gemm16_relu_bf16out(A0, w16, ff_b1, h16, MTOK, DFF, DMODEL);
    conv_f2bf(ff_w2, w16, DFF * DMODEL);
    launch_gemm16(h16, w16, ff_b2, t, MTOK, DMODEL, DFF);
    add_ln_kernel<<<MTOK, blk>>>(x2, t, ln3_g, ln3_b, out, nullptr);
}

// round 15
// speedup vs baseline: 4.5777x; 1.0648x over previous
#include <cuda_runtime.h>
#include <cuda_bf16.h>
#include <cstdint>
#include <mma.h>

using namespace nvcuda;

#define DMODEL 1024
#define NHEAD  16
#define DKH    64
#define DFF    4096
#define BATCH  4
#define SEQ    2048
#define MTOK   (BATCH * SEQ)

// ---------------- scratch (device globals; no allocation allowed) -------------
__device__ float g_x1[MTOK * DMODEL];
__device__ float g_x2[MTOK * DMODEL];
__device__ float g_t[MTOK * DMODEL];
__device__ __nv_bfloat16 g_q16[MTOK * DMODEL];
__device__ __nv_bfloat16 g_k16[MTOK * DMODEL];
__device__ __nv_bfloat16 g_v16[MTOK * DMODEL];
__device__ __nv_bfloat16 g_a16[2 * MTOK * DMODEL];  // two activation slots
__device__ __nv_bfloat16 g_h16[MTOK * DFF];         // FF hidden (bf16)
__device__ __nv_bfloat16 g_w16[DMODEL * DFF];       // weight scratch

// ---------------- fp32 -> bf16 conversion ------------------------------------
__global__ __launch_bounds__(256) void f2bf_kernel(
    const float* __restrict__ in, __nv_bfloat16* __restrict__ out, int n4)
{
    int i = blockIdx.x * blockDim.x + threadIdx.x;
    if (i < n4) {
        float4 v = reinterpret_cast<const float4*>(in)[i];
        __nv_bfloat162 a = __floats2bfloat162_rn(v.x, v.y);
        __nv_bfloat162 b = __floats2bfloat162_rn(v.z, v.w);
        uint2 u;
        u.x = *reinterpret_cast<unsigned*>(&a);
        u.y = *reinterpret_cast<unsigned*>(&b);
        reinterpret_cast<uint2*>(out)[i] = u;
    }
}

// ---------------- cp.async helper ---------------------------------------------
__device__ __forceinline__ void cp16(void* dst, const void* src) {
    unsigned d = (unsigned)__cvta_generic_to_shared(dst);
    asm volatile("cp.async.cg.shared.global [%0], [%1], 16;\n" :: "r"(d), "l"(src));
}

// ---------------- bf16 WMMA GEMM -----------------------------------------------
// BM=256, BN=128, BK=64; 8 warps, warp tile 64x64. 3-stage cp.async ring.
// OUT16=0: fp32 out to Cf.  OUT16=1: bf16 out to C16 (smem staging).
template <int RELU, int OUT16>
__global__ __launch_bounds__(256) void bf16_gemm_bias(
    const __nv_bfloat16* __restrict__ A, const __nv_bfloat16* __restrict__ W,
    const float* __restrict__ bias, float* __restrict__ Cf,
    __nv_bfloat16* __restrict__ C16, int M, int N, int K)
{
    constexpr int BM = 256, BN = 128, BK = 64;
    constexpr int LDA = 72;            // row stride 144B (16B multiple)
    constexpr int LDB = 136;           // row stride 272B (16B multiple)
    constexpr int ASTG = BM * LDA;     // 18432 elems per stage
    constexpr int BSTG = BK * LDB;     // 8704 elems per stage
    extern __shared__ __nv_bfloat16 gs[];
    __nv_bfloat16* const Asm = gs;
    __nv_bfloat16* const Bsm = gs + 3 * ASTG;

    const int tid = threadIdx.x;
    const int wid = tid >> 5;
    const int wm  = wid >> 1;
    const int wn  = wid & 1;
    const int bm  = blockIdx.y * BM;
    const int bn  = blockIdx.x * BN;

    wmma::fragment<wmma::accumulator, 16, 16, 16, float> acc[4][4];

    {
        float* fs = reinterpret_cast<float*>(gs);
        int rr = tid >> 5;
        int n4 = (tid & 31) << 2;
        float4 bv = *reinterpret_cast<const float4*>(bias + bn + n4);
        *reinterpret_cast<float4*>(&fs[rr * 136 + n4])       = bv;
        *reinterpret_cast<float4*>(&fs[(rr + 8) * 136 + n4]) = bv;
        __syncthreads();
        #pragma unroll
        for (int fc = 0; fc < 4; fc++) {
            wmma::load_matrix_sync(acc[0][fc], &fs[wn * 64 + fc * 16], 136,
                                   wmma::mem_row_major);
            #pragma unroll
            for (int fr = 1; fr < 4; fr++)
                #pragma unroll
                for (int e = 0; e < acc[0][fc].num_elements; e++)
                    acc[fr][fc].x[e] = acc[0][fc].x[e];
        }
        __syncthreads();
    }

    const __nv_bfloat16* const Ab = A + (size_t)bm * K;
    const __nv_bfloat16* const Wb = W + bn;

#define GISS(st, k0)                                                             \
    do {                                                                         \
        __nv_bfloat16* as = Asm + (st) * ASTG;                                   \
        __nv_bfloat16* bs = Bsm + (st) * BSTG;                                   \
        _Pragma("unroll")                                                        \
        for (int i = 0; i < 8; i++) {                                            \
            int idx = tid + i * 256;                                             \
            int r = idx >> 3, c8 = (idx & 7) * 8;                                \
            cp16(&as[r * LDA + c8], Ab + (size_t)r * K + (k0) + c8);             \
        }                                                                        \
        _Pragma("unroll")                                                        \
        for (int i = 0; i < 4; i++) {                                            \
            int idx = tid + i * 256;                                             \
            int r = idx >> 4, c8 = (idx & 15) * 8;                               \
            cp16(&bs[r * LDB + c8], Wb + (size_t)((k0) + r) * N + c8);           \
        }                                                                        \
        asm volatile("cp.async.commit_group;\n");                                \
    } while (0)

    const int NS = K / BK;
    GISS(0, 0);
    if (NS > 1) GISS(1, BK);

    int st = 0;
    for (int s = 0; s < NS; s++) {
        if (s + 1 < NS) asm volatile("cp.async.wait_group 1;\n");
        else            asm volatile("cp.async.wait_group 0;\n");
        __syncthreads();

        const __nv_bfloat16* as = Asm + st * ASTG;
        const __nv_bfloat16* bs = Bsm + st * BSTG;
        #pragma unroll
        for (int kk = 0; kk < BK; kk += 16) {
            wmma::fragment<wmma::matrix_a, 16, 16, 16, __nv_bfloat16,
                           wmma::row_major> af[4];
            wmma::fragment<wmma::matrix_b, 16, 16, 16, __nv_bfloat16,
                           wmma::row_major> bf[4];
            #pragma unroll
            for (int fr = 0; fr < 4; fr++)
                wmma::load_matrix_sync(af[fr], &as[(wm * 64 + fr * 16) * LDA + kk], LDA);
            #pragma unroll
            for (int fc = 0; fc < 4; fc++)
                wmma::load_matrix_sync(bf[fc], &bs[kk * LDB + wn * 64 + fc * 16], LDB);
            #pragma unroll
            for (int fr = 0; fr < 4; fr++)
                #pragma unroll
                for (int fc = 0; fc < 4; fc++)
                    wmma::mma_sync(acc[fr][fc], af[fr], bf[fc], acc[fr][fc]);
        }

        if (s + 2 < NS) {
            int nst = (st + 2) % 3;
            GISS(nst, (s + 2) * BK);
        }
        st = (st + 1) % 3;
    }
#undef GISS

    if (OUT16) {
        __syncthreads();
        float* stg = reinterpret_cast<float*>(gs) + wid * 256;
        const int lane = tid & 31;
        const int row  = lane >> 1;
        const int col  = (lane & 1) * 8;
        #pragma unroll
        for (int fr = 0; fr < 4; fr++)
            #pragma unroll
            for (int fc = 0; fc < 4; fc++) {
                if (RELU) {
                    #pragma unroll
                    for (int e = 0; e < acc[fr][fc].num_elements; e++)
                        acc[fr][fc].x[e] = fmaxf(acc[fr][fc].x[e], 0.0f);
                }
                wmma::store_matrix_sync(stg, acc[fr][fc], 16, wmma::mem_row_major);
                __syncwarp();
                float4 a  = *reinterpret_cast<float4*>(&stg[row * 16 + col]);
                float4 b4 = *reinterpret_cast<float4*>(&stg[row * 16 + col + 4]);
                __nv_bfloat162 p0 = __floats2bfloat162_rn(a.x,  a.y);
                __nv_bfloat162 p1 = __floats2bfloat162_rn(a.z,  a.w);
                __nv_bfloat162 p2 = __floats2bfloat162_rn(b4.x, b4.y);
                __nv_bfloat162 p3 = __floats2bfloat162_rn(b4.z, b4.w);
                uint4 u;
                u.x = *reinterpret_cast<unsigned*>(&p0);
                u.y = *reinterpret_cast<unsigned*>(&p1);
                u.z = *reinterpret_cast<unsigned*>(&p2);
                u.w = *reinterpret_cast<unsigned*>(&p3);
                *reinterpret_cast<uint4*>(
                    C16 + (size_t)(bm + wm * 64 + fr * 16 + row) * N
                        + bn + wn * 64 + fc * 16 + col) = u;
                __syncwarp();
            }
    } else {
        #pragma unroll
        for (int fr = 0; fr < 4; fr++)
            #pragma unroll
            for (int fc = 0; fc < 4; fc++) {
                if (RELU) {
                    #pragma unroll
                    for (int e = 0; e < acc[fr][fc].num_elements; e++)
                        acc[fr][fc].x[e] = fmaxf(acc[fr][fc].x[e], 0.0f);
                }
                float* cp = Cf + (size_t)(bm + wm * 64 + fr * 16) * N
                               + bn + wn * 64 + fc * 16;
                wmma::store_matrix_sync(cp, acc[fr][fc], N, wmma::mem_row_major);
            }
    }
}

#define GSMEM_BYTES ((3 * (256 * 72) + 3 * (64 * 136)) * 2)   // 162816

// ============== bf16 tensor-core flash attention (m16n8k16, dk=64) ============
#define HLDK 72
#define HLDV 72
#define HLDP 72
#define HKSTG (64 * HLDK)
#define HVT_OFF (2 * HKSTG)
#define HVSTG (64 * HLDV)
#define HPS_OFF (HVT_OFF + 2 * HVSTG)
#define HSMEM_H (HPS_OFF + 128 * HLDP)
#define HSMEM_BYTES (HSMEM_H * 2)

__device__ __forceinline__ void mma_bf16(float* d, const unsigned* a,
                                         const unsigned* b) {
    asm volatile(
        "mma.sync.aligned.m16n8k16.row.col.f32.bf16.bf16.f32 "
        "{%0,%1,%2,%3}, {%4,%5,%6,%7}, {%8,%9}, {%0,%1,%2,%3};\n"
        : "+f"(d[0]), "+f"(d[1]), "+f"(d[2]), "+f"(d[3])
        : "r"(a[0]), "r"(a[1]), "r"(a[2]), "r"(a[3]), "r"(b[0]), "r"(b[1]));
}

__global__ __launch_bounds__(256) void flash_attn_bf16(
    const __nv_bfloat16* __restrict__ Qg, const __nv_bfloat16* __restrict__ Kg,
    const __nv_bfloat16* __restrict__ Vg, __nv_bfloat16* __restrict__ Og16,
    int Sq, int Skv)
{
    extern __shared__ __nv_bfloat16 hsm[];
    unsigned* smw = reinterpret_cast<unsigned*>(hsm);

    const int tid  = threadIdx.x;
    const int lane = tid & 31;
    const int w    = tid >> 5;
    const int q0   = blockIdx.x * 128;
    const int h    = blockIdx.y;
    const int b    = blockIdx.z;
    const int r0   = lane >> 2;
    const int cq   = lane & 3;

    const int kc0 = tid, kc1 = tid + 256;
#define KISS(st, kvoff)                                                          \
    do {                                                                         \
        __nv_bfloat16* kb = hsm + (st) * HKSTG;                                  \
        { int r = kc0 >> 3, o8 = (kc0 & 7) * 8;                                  \
          cp16(&kb[r * HLDK + o8],                                               \
               Kg + (size_t)(b * Skv + (kvoff) + r) * DMODEL + h * DKH + o8); }  \
        { int r = kc1 >> 3, o8 = (kc1 & 7) * 8;                                  \
          cp16(&kb[r * HLDK + o8],                                               \
               Kg + (size_t)(b * Skv + (kvoff) + r) * DMODEL + h * DKH + o8); }  \
        asm volatile("cp.async.commit_group;\n");                                \
    } while (0)

    const int vc = tid & 63;
    const int vd = (tid >> 6) * 16;
    uint4 vr0, vr1;
#define VLOAD(kvoff)                                                             \
    do {                                                                         \
        const uint4* vp = reinterpret_cast<const uint4*>(                        \
            Vg + (size_t)(b * Skv + (kvoff) + vc) * DMODEL + h * DKH + vd);      \
        vr0 = vp[0]; vr1 = vp[1];                                                \
    } while (0)

    KISS(0, 0);
    VLOAD(0);

    unsigned qa[4][4];
    {
        const __nv_bfloat162 s2 = __float2bfloat162_rn(0.125f);
        const __nv_bfloat16* Qb = Qg + (size_t)(b * Sq + q0 + w * 16) * DMODEL + h * DKH;
        #pragma unroll
        for (int ds = 0; ds < 4; ds++) {
            #pragma unroll
            for (int p = 0; p < 4; p++) {
                int rr = (p & 1) ? r0 + 8 : r0;
                int cc = ds * 16 + 2 * cq + ((p & 2) ? 8 : 0);
                __nv_bfloat162 x = *reinterpret_cast<const __nv_bfloat162*>(
                    Qb + (size_t)rr * DMODEL + cc);
                x = __hmul2(x, s2);
                qa[ds][p] = *reinterpret_cast<unsigned*>(&x);
            }
        }
    }

    float m0 = -1e30f, m1 = -1e30f, l0 = 0.0f, l1 = 0.0f;
    float o[8][4];
    #pragma unroll
    for (int nt = 0; nt < 8; nt++)
        o[nt][0] = o[nt][1] = o[nt][2] = o[nt][3] = 0.0f;

    unsigned* const pw = smw + (HPS_OFF >> 1) + (w * 16) * (HLDP >> 1);
    const int NS = Skv / 64;

    for (int s = 0; s < NS; s++) {
        {
            __nv_bfloat16* vt = hsm + HVT_OFF + (s & 1) * HVSTG;
            __nv_bfloat16 tmp[16];
            *reinterpret_cast<uint4*>(tmp)     = vr0;
            *reinterpret_cast<uint4*>(tmp + 8) = vr1;
            #pragma unroll
            for (int j = 0; j < 16; j++)
                vt[(vd + j) * HLDV + vc] = tmp[j];
        }
        if (s + 1 < NS) {
            __syncthreads();
            KISS((s + 1) & 1, (s + 1) * 64);
            VLOAD((s + 1) * 64);
            asm volatile("cp.async.wait_group 1;\n");
        } else {
            asm volatile("cp.async.wait_group 0;\n");
        }
        __syncthreads();

        const unsigned* kw  = smw + (((s & 1) * HKSTG) >> 1);
        const unsigned* vtw = smw + ((HVT_OFF + (s & 1) * HVSTG) >> 1);

        float sc[8][4];
        #pragma unroll
        for (int nt = 0; nt < 8; nt++)
            sc[nt][0] = sc[nt][1] = sc[nt][2] = sc[nt][3] = 0.0f;

        #pragma unroll
        for (int ds = 0; ds < 4; ds++) {
            #pragma unroll
            for (int nt = 0; nt < 8; nt++) {
                const unsigned* kp = kw + (nt * 8 + r0) * 36 + ds * 8 + cq;
                unsigned bb[2] = { kp[0], kp[4] };
                mma_bf16(sc[nt], qa[ds], bb);
            }
        }

        float mx0 = sc[0][0], mx1 = sc[0][2];
        #pragma unroll
        for (int nt = 0; nt < 8; nt++) {
            mx0 = fmaxf(mx0, fmaxf(sc[nt][0], sc[nt][1]));
            mx1 = fmaxf(mx1, fmaxf(sc[nt][2], sc[nt][3]));
        }
        mx0 = fmaxf(mx0, __shfl_xor_sync(0xffffffffu, mx0, 1));
        mx0 = fmaxf(mx0, __shfl_xor_sync(0xffffffffu, mx0, 2));
        mx1 = fmaxf(mx1, __shfl_xor_sync(0xffffffffu, mx1, 1));
        mx1 = fmaxf(mx1, __shfl_xor_sync(0xffffffffu, mx1, 2));

        float mn0 = fmaxf(m0, mx0), mn1 = fmaxf(m1, mx1);
        float al0 = __expf(m0 - mn0), al1 = __expf(m1 - mn1);
        m0 = mn0; m1 = mn1;

        float sum0 = 0.0f, sum1 = 0.0f;
        #pragma unroll
        for (int nt = 0; nt < 8; nt++) {
            sc[nt][0] = __expf(sc[nt][0] - mn0);
            sc[nt][1] = __expf(sc[nt][1] - mn0);
            sc[nt][2] = __expf(sc[nt][2] - mn1);
            sc[nt][3] = __expf(sc[nt][3] - mn1);
            sum0 += sc[nt][0] + sc[nt][1];
            sum1 += sc[nt][2] + sc[nt][3];
        }
        sum0 += __shfl_xor_sync(0xffffffffu, sum0, 1);
        sum0 += __shfl_xor_sync(0xffffffffu, sum0, 2);
        sum1 += __shfl_xor_sync(0xffffffffu, sum1, 1);
        sum1 += __shfl_xor_sync(0xffffffffu, sum1, 2);
        l0 = l0 * al0 + sum0;
        l1 = l1 * al1 + sum1;

        #pragma unroll
        for (int nt = 0; nt < 8; nt++) {
            o[nt][0] *= al0; o[nt][1] *= al0;
            o[nt][2] *= al1; o[nt][3] *= al1;
            __nv_bfloat162 p01 = __floats2bfloat162_rn(sc[nt][0], sc[nt][1]);
            __nv_bfloat162 p23 = __floats2bfloat162_rn(sc[nt][2], sc[nt][3]);
            pw[r0 * 36 + nt * 4 + cq]       = *reinterpret_cast<unsigned*>(&p01);
            pw[(r0 + 8) * 36 + nt * 4 + cq] = *reinterpret_cast<unsigned*>(&p23);
        }
        __syncwarp();

        #pragma unroll
        for (int kk = 0; kk < 4; kk++) {
            unsigned pa[4];
            pa[0] = pw[r0 * 36 + kk * 8 + cq];
            pa[1] = pw[(r0 + 8) * 36 + kk * 8 + cq];
            pa[2] = pw[r0 * 36 + kk * 8 + cq + 4];
            pa[3] = pw[(r0 + 8) * 36 + kk * 8 + cq + 4];
            #pragma unroll
            for (int nt = 0; nt < 8; nt++) {
                const unsigned* vp = vtw + (nt * 8 + r0) * 36 + kk * 8 + cq;
                unsigned bb[2] = { vp[0], vp[4] };
                mma_bf16(o[nt], pa, bb);
            }
        }
    }
#undef KISS
#undef VLOAD

    const float i0 = 1.0f / l0, i1 = 1.0f / l1;
    __nv_bfloat16* Ob = Og16 + (size_t)(b * Sq + q0 + w * 16) * DMODEL + h * DKH;
    #pragma unroll
    for (int nt = 0; nt < 8; nt++) {
        __nv_bfloat162 v0 = __floats2bfloat162_rn(o[nt][0] * i0, o[nt][1] * i0);
        __nv_bfloat162 v1 = __floats2bfloat162_rn(o[nt][2] * i1, o[nt][3] * i1);
        *reinterpret_cast<unsigned*>(Ob + (size_t)r0 * DMODEL + nt * 8 + 2 * cq) =
            *reinterpret_cast<unsigned*>(&v0);
        *reinterpret_cast<unsigned*>(Ob + (size_t)(r0 + 8) * DMODEL + nt * 8 + 2 * cq) =
            *reinterpret_cast<unsigned*>(&v1);
    }
}

// ---------------- out = LayerNorm(a + c) * g + b  (+ optional bf16 copy) ------
__global__ __launch_bounds__(256) void add_ln_kernel(
    const float* __restrict__ a, const float* __restrict__ cadd,
    const float* __restrict__ g, const float* __restrict__ be,
    float* __restrict__ out, __nv_bfloat16* __restrict__ out16)
{
    __shared__ float red[16];
    const int row = blockIdx.x;
    const int tid = threadIdx.x;
    const size_t base = (size_t)row * DMODEL + tid * 4;

    float4 av = *reinterpret_cast<const float4*>(a + base);
    float4 cv = *reinterpret_cast<const float4*>(cadd + base);
    float x0 = av.x + cv.x, x1 = av.y + cv.y;
    float x2 = av.z + cv.z, x3 = av.w + cv.w;

    float s  = x0 + x1 + x2 + x3;
    float ss = x0 * x0 + x1 * x1 + x2 * x2 + x3 * x3;
    #pragma unroll
    for (int off = 16; off; off >>= 1) {
        s  += __shfl_xor_sync(0xffffffffu, s,  off);
        ss += __shfl_xor_sync(0xffffffffu, ss, off);
    }
    if ((tid & 31) == 0) { red[tid >> 5] = s; red[8 + (tid >> 5)] = ss; }
    __syncthreads();
    float ts = 0.0f, tss = 0.0f;
    #pragma unroll
    for (int i = 0; i < 8; i++) { ts += red[i]; tss += red[8 + i]; }

    const float mu  = ts * (1.0f / DMODEL);
    const float var = tss * (1.0f / DMODEL) - mu * mu;
    const float inv = rsqrtf(var + 1e-5f);

    float4 gv = *reinterpret_cast<const float4*>(g  + tid * 4);
    float4 bv = *reinterpret_cast<const float4*>(be + tid * 4);
    float4 ov;
    ov.x = (x0 - mu) * inv * gv.x + bv.x;
    ov.y = (x1 - mu) * inv * gv.y + bv.y;
    ov.z = (x2 - mu) * inv * gv.z + bv.z;
    ov.w = (x3 - mu) * inv * gv.w + bv.w;
    *reinterpret_cast<float4*>(out + base) = ov;

    if (out16) {
        __nv_bfloat162 p0 = __floats2bfloat162_rn(ov.x, ov.y);
        __nv_bfloat162 p1 = __floats2bfloat162_rn(ov.z, ov.w);
        uint2 u;
        u.x = *reinterpret_cast<unsigned*>(&p0);
        u.y = *reinterpret_cast<unsigned*>(&p1);
        *reinterpret_cast<uint2*>(out16 + base) = u;
    }
}

// ------------------------------- host driver ----------------------------------
static inline void conv_f2bf(const float* in, __nv_bfloat16* out, int n) {
    int n4 = n >> 2;
    f2bf_kernel<<<(n4 + 255) / 256, 256>>>(in, out, n4);
}

static inline void launch_gemm16(const __nv_bfloat16* A, const __nv_bfloat16* W,
                                 const float* B, float* Cf, int M, int N, int K)
{
    dim3 grid(N / 128, M / 256), blk(256);
    bf16_gemm_bias<0, 0><<<grid, blk, GSMEM_BYTES>>>(A, W, B, Cf, nullptr, M, N, K);
}

static inline void launch_gemm16_bf16out(
    const __nv_bfloat16* A, const __nv_bfloat16* W,
    const float* B, __nv_bfloat16* C16, int M, int N, int K)
{
    dim3 grid(N / 128, M / 256), blk(256);
    bf16_gemm_bias<0, 1><<<grid, blk, GSMEM_BYTES>>>(A, W, B, nullptr, C16, M, N, K);
}

static inline void launch_gemm16_relu_bf16out(
    const __nv_bfloat16* A, const __nv_bfloat16* W,
    const float* B, __nv_bfloat16* C16, int M, int N, int K)
{
    dim3 grid(N / 128, M / 256), blk(256);
    bf16_gemm_bias<1, 1><<<grid, blk, GSMEM_BYTES>>>(A, W, B, nullptr, C16, M, N, K);
}

extern "C" void kernel_launch(void* const* d_in, const int* in_sizes, int n_in,
                              void* d_out, int out_size)
{
    const float* src   = (const float*)d_in[0];
    const float* tgt   = (const float*)d_in[1];
    const float* sa_wq = (const float*)d_in[2];
    const float* sa_bq = (const float*)d_in[3];
    const float* sa_wk = (const float*)d_in[4];
    const float* sa_bk = (const float*)d_in[5];
    const float* sa_wv = (const float*)d_in[6];
    const float* sa_bv = (const float*)d_in[7];
    const float* sa_wo = (const float*)d_in[8];
    const float* sa_bo = (const float*)d_in[9];
    const float* ca_wq = (const float*)d_in[10];
    const float* ca_bq = (const float*)d_in[11];
    const float* ca_wk = (const float*)d_in[12];
    const float* ca_bk = (const float*)d_in[13];
    const float* ca_wv = (const float*)d_in[14];
    const float* ca_bv = (const float*)d_in[15];
    const float* ca_wo = (const float*)d_in[16];
    const float* ca_bo = (const float*)d_in[17];
    const float* ff_w1 = (const float*)d_in[18];
    const float* ff_b1 = (const float*)d_in[19];
    const float* ff_w2 = (const float*)d_in[20];
    const float* ff_b2 = (const float*)d_in[21];
    const float* ln1_g = (const float*)d_in[22];
    const float* ln1_b = (const float*)d_in[23];
    const float* ln2_g = (const float*)d_in[24];
    const float* ln2_b = (const float*)d_in[25];
    const float* ln3_g = (const float*)d_in[26];
    const float* ln3_b = (const float*)d_in[27];
    float* out = (float*)d_out;

    float *x1, *x2, *t;
    __nv_bfloat16 *q16, *k16, *v16, *a16, *h16, *w16;
    cudaGetSymbolAddress((void**)&x1,  g_x1);
    cudaGetSymbolAddress((void**)&x2,  g_x2);
    cudaGetSymbolAddress((void**)&t,   g_t);
    cudaGetSymbolAddress((void**)&q16, g_q16);
    cudaGetSymbolAddress((void**)&k16, g_k16);
    cudaGetSymbolAddress((void**)&v16, g_v16);
    cudaGetSymbolAddress((void**)&a16, g_a16);
    cudaGetSymbolAddress((void**)&h16, g_h16);
    cudaGetSymbolAddress((void**)&w16, g_w16);

    const int NMM = MTOK * DMODEL;
    const int NW  = DMODEL * DMODEL;
    __nv_bfloat16* A0 = a16;
    __nv_bfloat16* A1 = a16 + NMM;

    cudaFuncSetAttribute(flash_attn_bf16,
                         cudaFuncAttributeMaxDynamicSharedMemorySize, HSMEM_BYTES);
    cudaFuncSetAttribute(bf16_gemm_bias<0, 0>,
                         cudaFuncAttributeMaxDynamicSharedMemorySize, GSMEM_BYTES);
    cudaFuncSetAttribute(bf16_gemm_bias<0, 1>,
                         cudaFuncAttributeMaxDynamicSharedMemorySize, GSMEM_BYTES);
    cudaFuncSetAttribute(bf16_gemm_bias<1, 1>,
                         cudaFuncAttributeMaxDynamicSharedMemorySize, GSMEM_BYTES);

    dim3 fgrid(SEQ / 128, NHEAD, BATCH), blk(256);

    // ---- self-attention block ----
    conv_f2bf(tgt, A0, NMM);
    conv_f2bf(sa_wq, w16, NW);
    launch_gemm16_bf16out(A0, w16, sa_bq, q16, MTOK, DMODEL, DMODEL);
    conv_f2bf(sa_wk, w16, NW);
    launch_gemm16_bf16out(A0, w16, sa_bk, k16, MTOK, DMODEL, DMODEL);
    conv_f2bf(sa_wv, w16, NW);
    launch_gemm16_bf16out(A0, w16, sa_bv, v16, MTOK, DMODEL, DMODEL);
    flash_attn_bf16<<<fgrid, blk, HSMEM_BYTES>>>(q16, k16, v16, A1, SEQ, SEQ);
    conv_f2bf(sa_wo, w16, NW);
    launch_gemm16(A1, w16, sa_bo, t, MTOK, DMODEL, DMODEL);
    add_ln_kernel<<<MTOK, blk>>>(tgt, t, ln1_g, ln1_b, x1, A0);

    // ---- cross-attention block ----
    conv_f2bf(ca_wq, w16, NW);
    launch_gemm16_bf16out(A0, w16, ca_bq, q16, MTOK, DMODEL, DMODEL);
    conv_f2bf(src, A1, NMM);
    conv_f2bf(ca_wk, w16, NW);
    launch_gemm16_bf16out(A1, w16, ca_bk, k16, MTOK, DMODEL, DMODEL);
    conv_f2bf(ca_wv, w16, NW);
    launch_gemm16_bf16out(A1, w16, ca_bv, v16, MTOK, DMODEL, DMODEL);
    flash_attn_bf16<<<fgrid, blk, HSMEM_BYTES>>>(q16, k16, v16, A1, SEQ, SEQ);
    conv_f2bf(ca_wo, w16, NW);
    launch_gemm16(A1, w16, ca_bo, t, MTOK, DMODEL, DMODEL);
    add_ln_kernel<<<MTOK, blk>>>(x1, t, ln2_g, ln2_b, x2, A0);

    // ---- feed-forward block ----
    conv_f2bf(ff_w1, w16, DMODEL * DFF);
    launch_gemm16_relu_bf16out(A0, w16, ff_b1, h16, MTOK, DFF, DMODEL);
    conv_f2bf(ff_w2, w16, DFF * DMODEL);
    launch_gemm16(h16, w16, ff_b2, t, MTOK, DMODEL, DFF);
    add_ln_kernel<<<MTOK, blk>>>(x2, t, ln3_g, ln3_b, out, nullptr);
}